// round 1
// baseline (speedup 1.0000x reference)
#include <cuda_runtime.h>
#include <math.h>

#define BB   2
#define CC   128
#define HH   512
#define WW   512
#define NWIN 4096
#define NWF  1228
#define TOK  64      // tokens per window (8x8)
#define PTOK 64      // pooled tokens (8x8)
#define RS   129     // padded row stride for 64x128 smem tiles
#define SS   65      // padded row stride for 64x64 score tile
#define SCALE 0.08838834764831845f   // 128^-0.5

// -------- device scratch (static, no allocation) --------
__device__ float d_score[BB * NWIN];
__device__ int   d_sel[BB * NWF];
__device__ float d_g [BB * PTOK * CC];
__device__ float d_kg[BB * PTOK * CC];
__device__ float d_vg[BB * PTOK * CC];

// ================= score kernel =================
__global__ void score_kernel(const float* __restrict__ unc) {
    int id = blockIdx.x * blockDim.x + threadIdx.x;
    if (id >= BB * NWIN) return;
    int b = id / NWIN, w = id % NWIN;
    int hy = w >> 6, wx = w & 63;
    const float* base = unc + (size_t)b * HH * WW + (size_t)hy * 8 * WW + wx * 8;
    float s = 0.f;
    #pragma unroll
    for (int iy = 0; iy < 8; iy++)
        #pragma unroll
        for (int ix = 0; ix < 8; ix++)
            s += base[iy * WW + ix];
    d_score[id] = s * (1.f / 64.f);
}

// ================= selection (bitonic sort, desc, lower-idx tiebreak) =================
__global__ void select_kernel() {
    __shared__ unsigned long long key[NWIN];
    int b = blockIdx.x;
    int tid = threadIdx.x;
    for (int i = tid; i < NWIN; i += blockDim.x) {
        unsigned int sb = __float_as_uint(d_score[b * NWIN + i]);
        // positive floats: bit pattern is order-preserving.
        // lower index should win ties in descending order -> larger low bits.
        key[i] = (((unsigned long long)sb) << 12) | (unsigned)(NWIN - 1 - i);
    }
    __syncthreads();
    for (int k = 2; k <= NWIN; k <<= 1) {
        for (int j = k >> 1; j > 0; j >>= 1) {
            for (int i = tid; i < NWIN; i += blockDim.x) {
                int ixj = i ^ j;
                if (ixj > i) {
                    unsigned long long a = key[i], c = key[ixj];
                    bool desc = ((i & k) == 0);
                    if (desc ? (a < c) : (a > c)) { key[i] = c; key[ixj] = a; }
                }
            }
            __syncthreads();
        }
    }
    for (int m = tid; m < NWF; m += blockDim.x)
        d_sel[b * NWF + m] = (NWIN - 1) - (int)(key[m] & 0xFFFULL);
}

// ================= global pooling: g[b][p][c] = mean of 64x64 block =================
__global__ void pool_kernel(const float* __restrict__ fm) {
    int bid = blockIdx.x;          // BB*CC*PTOK = 16384
    int b = bid >> 13;
    int c = (bid >> 6) & 127;
    int p = bid & 63;
    int p0 = p >> 3, p1 = p & 7;
    const float* base = fm + ((size_t)(b * CC + c) * HH + (size_t)p0 * 64) * WW + p1 * 64;
    float s = 0.f;
    for (int e = threadIdx.x; e < 4096; e += 128) {
        int r = e >> 6, col = e & 63;
        s += base[r * WW + col];
    }
    __shared__ float red[128];
    red[threadIdx.x] = s;
    __syncthreads();
    for (int off = 64; off > 0; off >>= 1) {
        if (threadIdx.x < off) red[threadIdx.x] += red[threadIdx.x + off];
        __syncthreads();
    }
    if (threadIdx.x == 0)
        d_g[(b * PTOK + p) * CC + c] = red[0] * (1.f / 4096.f);
}

// ================= global k/v projection =================
__global__ void kv_kernel(const float* __restrict__ kvw) {
    int id = blockIdx.x * blockDim.x + threadIdx.x;    // 32768
    int which = id >> 14;          // 0 = k, 1 = v
    int rem = id & 16383;
    int b = rem >> 13;
    int p = (rem >> 7) & 63;
    int c = rem & 127;
    const float* grow = d_g + (b * PTOK + p) * CC;
    const float* wrow = kvw + (size_t)(which * CC + c) * CC;
    float s = 0.f;
    #pragma unroll 8
    for (int j = 0; j < CC; j++) s += grow[j] * __ldg(&wrow[j]);
    (which ? d_vg : d_kg)[(b * PTOK + p) * CC + c] = s;
}

// ================= pass-through copy =================
__global__ void copy_kernel(const float4* __restrict__ in, float4* __restrict__ out, int n4) {
    int stride = gridDim.x * blockDim.x;
    for (int i = blockIdx.x * blockDim.x + threadIdx.x; i < n4; i += stride)
        out[i] = in[i];
}

// ================= per-window compute =================
// O[t][c] = sum_k A[t][k] * W[c][k]; A,O smem (stride RS), W global, Wt smem scratch 128x33
__device__ __forceinline__ void gemm_tw(const float* A, const float* __restrict__ W,
                                        float* O, float* Wt) {
    const int tid = threadIdx.x;
    const int r0 = (tid >> 4) * 4;
    const int c0 = (tid & 15) * 8;
    float acc[4][8];
    #pragma unroll
    for (int i = 0; i < 4; i++)
        #pragma unroll
        for (int j = 0; j < 8; j++) acc[i][j] = 0.f;
    for (int kt = 0; kt < 128; kt += 32) {
        __syncthreads();
        #pragma unroll
        for (int l = 0; l < 16; l++) {
            int idx = l * 256 + tid;
            int c = idx >> 5, k = idx & 31;
            Wt[c * 33 + k] = W[c * 128 + kt + k];
        }
        __syncthreads();
        #pragma unroll 8
        for (int k = 0; k < 32; k++) {
            float a[4], wv[8];
            #pragma unroll
            for (int i = 0; i < 4; i++) a[i] = A[(r0 + i) * RS + kt + k];
            #pragma unroll
            for (int j = 0; j < 8; j++) wv[j] = Wt[(c0 + j) * 33 + k];
            #pragma unroll
            for (int i = 0; i < 4; i++)
                #pragma unroll
                for (int j = 0; j < 8; j++) acc[i][j] = fmaf(a[i], wv[j], acc[i][j]);
        }
    }
    __syncthreads();
    #pragma unroll
    for (int i = 0; i < 4; i++)
        #pragma unroll
        for (int j = 0; j < 8; j++) O[(r0 + i) * RS + c0 + j] = acc[i][j];
}

// S[q][k] = dot(Q[q], K[k])  (raw logits, scale applied in softmax)
__device__ __forceinline__ void attn_scores(const float* Q, const float* K, float* S) {
    const int tid = threadIdx.x;
    const int r0 = (tid >> 4) * 4;
    const int c0 = (tid & 15) * 4;
    float acc[4][4];
    #pragma unroll
    for (int i = 0; i < 4; i++)
        #pragma unroll
        for (int j = 0; j < 4; j++) acc[i][j] = 0.f;
    #pragma unroll 4
    for (int k = 0; k < 128; k++) {
        float a[4], kk[4];
        #pragma unroll
        for (int i = 0; i < 4; i++) a[i] = Q[(r0 + i) * RS + k];
        #pragma unroll
        for (int j = 0; j < 4; j++) kk[j] = K[(c0 + j) * RS + k];
        #pragma unroll
        for (int i = 0; i < 4; i++)
            #pragma unroll
            for (int j = 0; j < 4; j++) acc[i][j] = fmaf(a[i], kk[j], acc[i][j]);
    }
    #pragma unroll
    for (int i = 0; i < 4; i++)
        #pragma unroll
        for (int j = 0; j < 4; j++) S[(r0 + i) * SS + c0 + j] = acc[i][j];
}

// per-row softmax of S (64x64, stride SS); 4 consecutive lanes per row
__device__ __forceinline__ void softmax_rows(float* S) {
    const int tid = threadIdx.x;
    const int r = tid >> 2, sub = tid & 3;
    float* row = S + r * SS;
    float mx = -1e30f;
    #pragma unroll
    for (int j = sub; j < 64; j += 4) mx = fmaxf(mx, row[j] * SCALE);
    mx = fmaxf(mx, __shfl_xor_sync(0xffffffffu, mx, 1));
    mx = fmaxf(mx, __shfl_xor_sync(0xffffffffu, mx, 2));
    float s = 0.f;
    #pragma unroll
    for (int j = sub; j < 64; j += 4) {
        float e = expf(row[j] * SCALE - mx);
        row[j] = e;
        s += e;
    }
    s += __shfl_xor_sync(0xffffffffu, s, 1);
    s += __shfl_xor_sync(0xffffffffu, s, 2);
    float inv = 1.f / s;
    #pragma unroll
    for (int j = sub; j < 64; j += 4) row[j] *= inv;
}

// O[q][c] (+)= sum_k S[q][k] * V[k][c]
__device__ __forceinline__ void gemm_av(const float* S, const float* V, float* O, bool accum) {
    const int tid = threadIdx.x;
    const int r0 = (tid >> 4) * 4;
    const int c0 = (tid & 15) * 8;
    float acc[4][8];
    #pragma unroll
    for (int i = 0; i < 4; i++)
        #pragma unroll
        for (int j = 0; j < 8; j++) acc[i][j] = 0.f;
    #pragma unroll 8
    for (int k = 0; k < 64; k++) {
        float a[4], vv[8];
        #pragma unroll
        for (int i = 0; i < 4; i++) a[i] = S[(r0 + i) * SS + k];
        #pragma unroll
        for (int j = 0; j < 8; j++) vv[j] = V[k * RS + c0 + j];
        #pragma unroll
        for (int i = 0; i < 4; i++)
            #pragma unroll
            for (int j = 0; j < 8; j++) acc[i][j] = fmaf(a[i], vv[j], acc[i][j]);
    }
    #pragma unroll
    for (int i = 0; i < 4; i++)
        #pragma unroll
        for (int j = 0; j < 8; j++) {
            if (accum) O[(r0 + i) * RS + c0 + j] += acc[i][j];
            else       O[(r0 + i) * RS + c0 + j]  = acc[i][j];
        }
}

__device__ __forceinline__ void gelu_add(float* WF, const float* B, const float* __restrict__ bias) {
    const int tid = threadIdx.x;
    for (int i = tid; i < TOK * CC; i += 256) {
        int t = i >> 7, c = i & 127;
        float x = B[t * RS + c] + bias[c];
        float g = 0.5f * x * (1.f + erff(x * 0.70710678118654752f));
        WF[t * RS + c] += g;
    }
}

__global__ __launch_bounds__(256) void window_kernel(
    const float* __restrict__ fm,
    const float* __restrict__ qgw,
    const float* __restrict__ l0w, const float* __restrict__ l0b,
    const float* __restrict__ qkvw,
    const float* __restrict__ pw, const float* __restrict__ pb,
    float* __restrict__ out)
{
    extern __shared__ float sm[];
    float* WF = sm;
    float* B1 = sm + TOK * RS;
    float* B2 = B1 + TOK * RS;
    float* B3 = B2 + TOK * RS;
    float* SC = B3 + TOK * RS;   // 4224 floats: scores (64x65) or W tile (128x33)

    const int tid = threadIdx.x;
    const int n = blockIdx.x;
    const int b = n / NWF;
    const int w = d_sel[n];
    const int hy = w >> 6, wx = w & 63;

    // gather window features + per-batch global k/v
    for (int i = tid; i < TOK * CC; i += 256) {
        int c = i >> 6, t = i & 63;
        WF[t * RS + c] = fm[((size_t)(b * CC + c) * HH + hy * 8 + (t >> 3)) * WW + wx * 8 + (t & 7)];
    }
    for (int i = tid; i < PTOK * CC; i += 256) {
        int p = i >> 7, c = i & 127;
        B2[p * RS + c] = d_kg[b * PTOK * CC + i];
        B3[p * RS + c] = d_vg[b * PTOK * CC + i];
    }

    // --- global cross-attention ---
    gemm_tw(WF, qgw, B1, SC);               // q = wf @ q_g_w^T
    __syncthreads();
    attn_scores(B1, B2, SC);
    __syncthreads();
    softmax_rows(SC);
    __syncthreads();
    gemm_av(SC, B3, WF, true);              // wf += attn @ v_g

    // --- MLP 1 ---
    gemm_tw(WF, l0w, B1, SC);
    __syncthreads();
    gelu_add(WF, B1, l0b);                  // wf += gelu(wf @ W + b)

    // --- window self-attention ---
    gemm_tw(WF, qkvw,            B1, SC);   // q2
    gemm_tw(WF, qkvw + 128*128,  B2, SC);   // k2
    gemm_tw(WF, qkvw + 256*128,  B3, SC);   // v2
    __syncthreads();
    attn_scores(B1, B2, SC);
    __syncthreads();
    softmax_rows(SC);
    __syncthreads();
    gemm_av(SC, B3, B1, false);             // av
    __syncthreads();
    // reference quirk: wf[t][j] += av[j%64][2t + j/64]
    for (int i = tid; i < TOK * CC; i += 256) {
        int t = i >> 7, j = i & 127;
        WF[t * RS + j] += B1[(j & 63) * RS + 2 * t + (j >> 6)];
    }

    // --- MLP 2 ---
    gemm_tw(WF, pw, B2, SC);
    __syncthreads();
    gelu_add(WF, B2, pb);
    __syncthreads();

    // scatter back
    for (int i = tid; i < TOK * CC; i += 256) {
        int c = i >> 6, t = i & 63;
        out[((size_t)(b * CC + c) * HH + hy * 8 + (t >> 3)) * WW + wx * 8 + (t & 7)] = WF[t * RS + c];
    }
}

// =====================================================================
extern "C" void kernel_launch(void* const* d_in, const int* in_sizes, int n_in,
                              void* d_out, int out_size) {
    const float* fm   = (const float*)d_in[0];
    const float* unc  = (const float*)d_in[1];
    const float* qgw  = (const float*)d_in[2];
    const float* kvw  = (const float*)d_in[3];
    const float* l0w  = (const float*)d_in[4];
    const float* l0b  = (const float*)d_in[5];
    const float* qkvw = (const float*)d_in[6];
    const float* pw   = (const float*)d_in[7];
    const float* pb   = (const float*)d_in[8];
    float* out = (float*)d_out;

    const int SMEM_BYTES = (4 * TOK * RS + 4224) * sizeof(float);   // 148,992 B
    cudaFuncSetAttribute(window_kernel, cudaFuncAttributeMaxDynamicSharedMemorySize, SMEM_BYTES);

    score_kernel<<<(BB * NWIN + 255) / 256, 256>>>(unc);
    select_kernel<<<BB, 1024>>>();
    pool_kernel<<<BB * CC * PTOK, 128>>>(fm);
    kv_kernel<<<(2 * BB * PTOK * CC) / 256, 256>>>(kvw);

    int n4 = BB * CC * HH * WW / 4;
    copy_kernel<<<4096, 256>>>((const float4*)fm, (float4*)out, n4);

    window_kernel<<<BB * NWF, 256, SMEM_BYTES>>>(fm, qgw, l0w, l0b, qkvw, pw, pb, out);
}

// round 2
// speedup vs baseline: 1.0008x; 1.0008x over previous
#include <cuda_runtime.h>
#include <math.h>

#define BB   2
#define CC   128
#define HH   512
#define WW   512
#define NWIN 4096
#define NWF  1228
#define TOK  64      // tokens per window (8x8)
#define PTOK 64      // pooled tokens (8x8)
#define RS   129     // padded row stride for 64x128 smem tiles
#define SS   65      // padded row stride for 64x64 score tile
#define SCALE 0.08838834764831845f   // 128^-0.5

// -------- device scratch (static, no allocation) --------
__device__ float d_score[BB * NWIN];
__device__ int   d_sel[BB * NWF];
__device__ float d_g [BB * PTOK * CC];
__device__ float d_kg[BB * PTOK * CC];
__device__ float d_vg[BB * PTOK * CC];

// ================= score kernel =================
__global__ void score_kernel(const float* __restrict__ unc) {
    int id = blockIdx.x * blockDim.x + threadIdx.x;
    if (id >= BB * NWIN) return;
    int b = id / NWIN, w = id % NWIN;
    int hy = w >> 6, wx = w & 63;
    const float* base = unc + (size_t)b * HH * WW + (size_t)hy * 8 * WW + wx * 8;
    float s = 0.f;
    #pragma unroll
    for (int iy = 0; iy < 8; iy++)
        #pragma unroll
        for (int ix = 0; ix < 8; ix++)
            s += base[iy * WW + ix];
    d_score[id] = s * (1.f / 64.f);
}

// ================= selection (bitonic sort, desc, lower-idx tiebreak) =================
__global__ void select_kernel() {
    __shared__ unsigned long long key[NWIN];
    int b = blockIdx.x;
    int tid = threadIdx.x;
    for (int i = tid; i < NWIN; i += blockDim.x) {
        unsigned int sb = __float_as_uint(d_score[b * NWIN + i]);
        // positive floats: bit pattern is order-preserving.
        // lower index should win ties in descending order -> larger low bits.
        key[i] = (((unsigned long long)sb) << 12) | (unsigned)(NWIN - 1 - i);
    }
    __syncthreads();
    for (int k = 2; k <= NWIN; k <<= 1) {
        for (int j = k >> 1; j > 0; j >>= 1) {
            for (int i = tid; i < NWIN; i += blockDim.x) {
                int ixj = i ^ j;
                if (ixj > i) {
                    unsigned long long a = key[i], c = key[ixj];
                    bool desc = ((i & k) == 0);
                    if (desc ? (a < c) : (a > c)) { key[i] = c; key[ixj] = a; }
                }
            }
            __syncthreads();
        }
    }
    for (int m = tid; m < NWF; m += blockDim.x)
        d_sel[b * NWF + m] = (NWIN - 1) - (int)(key[m] & 0xFFFULL);
}

// ================= global pooling: g[b][p][c] = mean of 64x64 block =================
__global__ void pool_kernel(const float* __restrict__ fm) {
    int bid = blockIdx.x;          // BB*CC*PTOK = 16384
    int b = bid >> 13;
    int c = (bid >> 6) & 127;
    int p = bid & 63;
    int p0 = p >> 3, p1 = p & 7;
    const float* base = fm + ((size_t)(b * CC + c) * HH + (size_t)p0 * 64) * WW + p1 * 64;
    float s = 0.f;
    for (int e = threadIdx.x; e < 4096; e += 128) {
        int r = e >> 6, col = e & 63;
        s += base[r * WW + col];
    }
    __shared__ float red[128];
    red[threadIdx.x] = s;
    __syncthreads();
    for (int off = 64; off > 0; off >>= 1) {
        if (threadIdx.x < off) red[threadIdx.x] += red[threadIdx.x + off];
        __syncthreads();
    }
    if (threadIdx.x == 0)
        d_g[(b * PTOK + p) * CC + c] = red[0] * (1.f / 4096.f);
}

// ================= global k/v projection =================
__global__ void kv_kernel(const float* __restrict__ kvw) {
    int id = blockIdx.x * blockDim.x + threadIdx.x;    // 32768
    int which = id >> 14;          // 0 = k, 1 = v
    int rem = id & 16383;
    int b = rem >> 13;
    int p = (rem >> 7) & 63;
    int c = rem & 127;
    const float* grow = d_g + (b * PTOK + p) * CC;
    const float* wrow = kvw + (size_t)(which * CC + c) * CC;
    float s = 0.f;
    #pragma unroll 8
    for (int j = 0; j < CC; j++) s += grow[j] * __ldg(&wrow[j]);
    (which ? d_vg : d_kg)[(b * PTOK + p) * CC + c] = s;
}

// ================= pass-through copy =================
__global__ void copy_kernel(const float4* __restrict__ in, float4* __restrict__ out, int n4) {
    int stride = gridDim.x * blockDim.x;
    for (int i = blockIdx.x * blockDim.x + threadIdx.x; i < n4; i += stride)
        out[i] = in[i];
}

// ================= per-window compute =================
// O[t][c] = sum_k A[t][k] * W[c][k]; A,O smem (stride RS), W global, Wt smem scratch 128x33
__device__ __forceinline__ void gemm_tw(const float* A, const float* __restrict__ W,
                                        float* O, float* Wt) {
    const int tid = threadIdx.x;
    const int r0 = (tid >> 4) * 4;
    const int c0 = (tid & 15) * 8;
    float acc[4][8];
    #pragma unroll
    for (int i = 0; i < 4; i++)
        #pragma unroll
        for (int j = 0; j < 8; j++) acc[i][j] = 0.f;
    for (int kt = 0; kt < 128; kt += 32) {
        __syncthreads();
        #pragma unroll
        for (int l = 0; l < 16; l++) {
            int idx = l * 256 + tid;
            int c = idx >> 5, k = idx & 31;
            Wt[c * 33 + k] = W[c * 128 + kt + k];
        }
        __syncthreads();
        #pragma unroll 8
        for (int k = 0; k < 32; k++) {
            float a[4], wv[8];
            #pragma unroll
            for (int i = 0; i < 4; i++) a[i] = A[(r0 + i) * RS + kt + k];
            #pragma unroll
            for (int j = 0; j < 8; j++) wv[j] = Wt[(c0 + j) * 33 + k];
            #pragma unroll
            for (int i = 0; i < 4; i++)
                #pragma unroll
                for (int j = 0; j < 8; j++) acc[i][j] = fmaf(a[i], wv[j], acc[i][j]);
        }
    }
    __syncthreads();
    #pragma unroll
    for (int i = 0; i < 4; i++)
        #pragma unroll
        for (int j = 0; j < 8; j++) O[(r0 + i) * RS + c0 + j] = acc[i][j];
}

// S[q][k] = dot(Q[q], K[k])  (raw logits, scale applied in softmax)
__device__ __forceinline__ void attn_scores(const float* Q, const float* K, float* S) {
    const int tid = threadIdx.x;
    const int r0 = (tid >> 4) * 4;
    const int c0 = (tid & 15) * 4;
    float acc[4][4];
    #pragma unroll
    for (int i = 0; i < 4; i++)
        #pragma unroll
        for (int j = 0; j < 4; j++) acc[i][j] = 0.f;
    #pragma unroll 4
    for (int k = 0; k < 128; k++) {
        float a[4], kk[4];
        #pragma unroll
        for (int i = 0; i < 4; i++) a[i] = Q[(r0 + i) * RS + k];
        #pragma unroll
        for (int j = 0; j < 4; j++) kk[j] = K[(c0 + j) * RS + k];
        #pragma unroll
        for (int i = 0; i < 4; i++)
            #pragma unroll
            for (int j = 0; j < 4; j++) acc[i][j] = fmaf(a[i], kk[j], acc[i][j]);
    }
    #pragma unroll
    for (int i = 0; i < 4; i++)
        #pragma unroll
        for (int j = 0; j < 4; j++) S[(r0 + i) * SS + c0 + j] = acc[i][j];
}

// per-row softmax of S (64x64, stride SS); 4 consecutive lanes per row
__device__ __forceinline__ void softmax_rows(float* S) {
    const int tid = threadIdx.x;
    const int r = tid >> 2, sub = tid & 3;
    float* row = S + r * SS;
    float mx = -1e30f;
    #pragma unroll
    for (int j = sub; j < 64; j += 4) mx = fmaxf(mx, row[j] * SCALE);
    mx = fmaxf(mx, __shfl_xor_sync(0xffffffffu, mx, 1));
    mx = fmaxf(mx, __shfl_xor_sync(0xffffffffu, mx, 2));
    float s = 0.f;
    #pragma unroll
    for (int j = sub; j < 64; j += 4) {
        float e = expf(row[j] * SCALE - mx);
        row[j] = e;
        s += e;
    }
    s += __shfl_xor_sync(0xffffffffu, s, 1);
    s += __shfl_xor_sync(0xffffffffu, s, 2);
    float inv = 1.f / s;
    #pragma unroll
    for (int j = sub; j < 64; j += 4) row[j] *= inv;
}

// O[q][c] (+)= sum_k S[q][k] * V[k][c]
__device__ __forceinline__ void gemm_av(const float* S, const float* V, float* O, bool accum) {
    const int tid = threadIdx.x;
    const int r0 = (tid >> 4) * 4;
    const int c0 = (tid & 15) * 8;
    float acc[4][8];
    #pragma unroll
    for (int i = 0; i < 4; i++)
        #pragma unroll
        for (int j = 0; j < 8; j++) acc[i][j] = 0.f;
    #pragma unroll 8
    for (int k = 0; k < 64; k++) {
        float a[4], vv[8];
        #pragma unroll
        for (int i = 0; i < 4; i++) a[i] = S[(r0 + i) * SS + k];
        #pragma unroll
        for (int j = 0; j < 8; j++) vv[j] = V[k * RS + c0 + j];
        #pragma unroll
        for (int i = 0; i < 4; i++)
            #pragma unroll
            for (int j = 0; j < 8; j++) acc[i][j] = fmaf(a[i], vv[j], acc[i][j]);
    }
    #pragma unroll
    for (int i = 0; i < 4; i++)
        #pragma unroll
        for (int j = 0; j < 8; j++) {
            if (accum) O[(r0 + i) * RS + c0 + j] += acc[i][j];
            else       O[(r0 + i) * RS + c0 + j]  = acc[i][j];
        }
}

__device__ __forceinline__ void gelu_add(float* WF, const float* B, const float* __restrict__ bias) {
    const int tid = threadIdx.x;
    for (int i = tid; i < TOK * CC; i += 256) {
        int t = i >> 7, c = i & 127;
        float x = B[t * RS + c] + bias[c];
        float g = 0.5f * x * (1.f + erff(x * 0.70710678118654752f));
        WF[t * RS + c] += g;
    }
}

__global__ __launch_bounds__(256) void window_kernel(
    const float* __restrict__ fm,
    const float* __restrict__ qgw,
    const float* __restrict__ l0w, const float* __restrict__ l0b,
    const float* __restrict__ qkvw,
    const float* __restrict__ pw, const float* __restrict__ pb,
    float* __restrict__ out)
{
    extern __shared__ float sm[];
    float* WF = sm;
    float* B1 = sm + TOK * RS;
    float* B2 = B1 + TOK * RS;
    float* B3 = B2 + TOK * RS;
    float* SC = B3 + TOK * RS;   // 4224 floats: scores (64x65) or W tile (128x33)

    const int tid = threadIdx.x;
    const int n = blockIdx.x;
    const int b = n / NWF;
    const int w = d_sel[n];
    const int hy = w >> 6, wx = w & 63;

    // gather window features + per-batch global k/v
    for (int i = tid; i < TOK * CC; i += 256) {
        int c = i >> 6, t = i & 63;
        WF[t * RS + c] = fm[((size_t)(b * CC + c) * HH + hy * 8 + (t >> 3)) * WW + wx * 8 + (t & 7)];
    }
    for (int i = tid; i < PTOK * CC; i += 256) {
        int p = i >> 7, c = i & 127;
        B2[p * RS + c] = d_kg[b * PTOK * CC + i];
        B3[p * RS + c] = d_vg[b * PTOK * CC + i];
    }

    // --- global cross-attention ---
    gemm_tw(WF, qgw, B1, SC);               // q = wf @ q_g_w^T
    __syncthreads();
    attn_scores(B1, B2, SC);
    __syncthreads();
    softmax_rows(SC);
    __syncthreads();
    gemm_av(SC, B3, WF, true);              // wf += attn @ v_g

    // --- MLP 1 ---
    gemm_tw(WF, l0w, B1, SC);
    __syncthreads();
    gelu_add(WF, B1, l0b);                  // wf += gelu(wf @ W + b)

    // --- window self-attention ---
    gemm_tw(WF, qkvw,            B1, SC);   // q2
    gemm_tw(WF, qkvw + 128*128,  B2, SC);   // k2
    gemm_tw(WF, qkvw + 256*128,  B3, SC);   // v2
    __syncthreads();
    attn_scores(B1, B2, SC);
    __syncthreads();
    softmax_rows(SC);
    __syncthreads();
    gemm_av(SC, B3, B1, false);             // av
    __syncthreads();
    // reference quirk: wf[t][j] += av[j%64][2t + j/64]
    for (int i = tid; i < TOK * CC; i += 256) {
        int t = i >> 7, j = i & 127;
        WF[t * RS + j] += B1[(j & 63) * RS + 2 * t + (j >> 6)];
    }

    // --- MLP 2 ---
    gemm_tw(WF, pw, B2, SC);
    __syncthreads();
    gelu_add(WF, B2, pb);
    __syncthreads();

    // scatter back
    for (int i = tid; i < TOK * CC; i += 256) {
        int c = i >> 6, t = i & 63;
        out[((size_t)(b * CC + c) * HH + hy * 8 + (t >> 3)) * WW + wx * 8 + (t & 7)] = WF[t * RS + c];
    }
}

// =====================================================================
extern "C" void kernel_launch(void* const* d_in, const int* in_sizes, int n_in,
                              void* d_out, int out_size) {
    const float* fm   = (const float*)d_in[0];
    const float* unc  = (const float*)d_in[1];
    const float* qgw  = (const float*)d_in[2];
    const float* kvw  = (const float*)d_in[3];
    const float* l0w  = (const float*)d_in[4];
    const float* l0b  = (const float*)d_in[5];
    const float* qkvw = (const float*)d_in[6];
    const float* pw   = (const float*)d_in[7];
    const float* pb   = (const float*)d_in[8];
    float* out = (float*)d_out;

    const int SMEM_BYTES = (4 * TOK * RS + 4224) * sizeof(float);   // 148,992 B
    cudaFuncSetAttribute(window_kernel, cudaFuncAttributeMaxDynamicSharedMemorySize, SMEM_BYTES);

    score_kernel<<<(BB * NWIN + 255) / 256, 256>>>(unc);
    select_kernel<<<BB, 1024>>>();
    pool_kernel<<<BB * CC * PTOK, 128>>>(fm);
    kv_kernel<<<(2 * BB * PTOK * CC) / 256, 256>>>(kvw);

    int n4 = BB * CC * HH * WW / 4;
    copy_kernel<<<4096, 256>>>((const float4*)fm, (float4*)out, n4);

    window_kernel<<<BB * NWF, 256, SMEM_BYTES>>>(fm, qgw, l0w, l0b, qkvw, pw, pb, out);
}

// round 4
// speedup vs baseline: 1.6424x; 1.6411x over previous
#include <cuda_runtime.h>
#include <cuda_bf16.h>
#include <math.h>
#include <stdint.h>

#define BB   2
#define CC   128
#define HH   512
#define WW   512
#define NWIN 4096
#define NWF  1228
#define NPAIR (NWF/2)
#define HWSZ ((size_t)HH*(size_t)WW)
#define SCALEF 0.08838834764831845f

// strides (elements)
#define SA 136      // 128-wide bf16 tiles
#define SP 72       // 64-wide bf16 tiles
#define SD 132      // fp32 dump stride

// smem byte offsets
#define O_A   1024              // WFH 128x136 bf16 = 34816
#define O_B   35840             // WFL
#define O_C   70656             // WTH (DUMP overlays C+D)
#define O_D   105472            // WTL
#define O_E   140288            // q / q2 / v2T  128x136
#define O_F   175104            // kg(64x136)+vgT(128x72) | k2(128x136)
#define O_VGT (O_F+17408)
#define O_P   210944            // P 128x72 bf16 = 18432
#define SMEM_SZ 229376

// -------- device scratch --------
__device__ float d_score[BB * NWIN];
__device__ int   d_sel[BB * NWF];
__device__ float d_g[BB * 64 * CC];
__device__ __nv_bfloat16 d_kgb[BB][64 * 128];    // kg[p][c]
__device__ __nv_bfloat16 d_vgtb[BB][128 * 64];   // vgT[c][p]

// ---------------- helpers ----------------
__device__ __forceinline__ uint32_t pkf(float a, float b){
    __nv_bfloat162 t = __floats2bfloat162_rn(a, b);
    return *reinterpret_cast<uint32_t*>(&t);
}
__device__ __forceinline__ float2 up2(uint32_t u){
    __nv_bfloat162 b = *reinterpret_cast<__nv_bfloat162*>(&u);
    return make_float2(__bfloat162float(b.x), __bfloat162float(b.y));
}
__device__ __forceinline__ void split2(float x0, float x1, uint32_t& h, uint32_t& l){
    __nv_bfloat16 b0 = __float2bfloat16_rn(x0), b1 = __float2bfloat16_rn(x1);
    __nv_bfloat162 hb; hb.x = b0; hb.y = b1;
    h = *reinterpret_cast<uint32_t*>(&hb);
    l = pkf(x0 - __bfloat162float(b0), x1 - __bfloat162float(b1));
}
__device__ __forceinline__ float geluf(float x){
    return 0.5f * x * (1.f + erff(x * 0.70710678118654752f));
}
__device__ __forceinline__ void mma16816(float* d, const uint32_t* a, uint32_t b0, uint32_t b1){
    asm("mma.sync.aligned.m16n8k16.row.col.f32.bf16.bf16.f32 "
        "{%0,%1,%2,%3},{%4,%5,%6,%7},{%8,%9},{%0,%1,%2,%3};"
        : "+f"(d[0]), "+f"(d[1]), "+f"(d[2]), "+f"(d[3])
        : "r"(a[0]), "r"(a[1]), "r"(a[2]), "r"(a[3]), "r"(b0), "r"(b1));
}

// warp computes rows [row0,row0+16) x cols [0, NT*8) ; A row-major [m][k], B row-major [n][k]
template<int NT, int KS>
__device__ __forceinline__ void gpass(float (*acc)[4],
                                      const __nv_bfloat16* A, int sA, int row0,
                                      const __nv_bfloat16* B, int sB, int bcol0,
                                      int g, int t){
    #pragma unroll
    for (int ks = 0; ks < KS; ks++){
        const int k0 = ks * 16;
        uint32_t a[4];
        a[0] = *(const uint32_t*)(A + (row0 + g)     * sA + k0 + 2*t);
        a[1] = *(const uint32_t*)(A + (row0 + 8 + g) * sA + k0 + 2*t);
        a[2] = *(const uint32_t*)(A + (row0 + g)     * sA + k0 + 2*t + 8);
        a[3] = *(const uint32_t*)(A + (row0 + 8 + g) * sA + k0 + 2*t + 8);
        #pragma unroll
        for (int nt = 0; nt < NT; nt++){
            uint32_t b0 = *(const uint32_t*)(B + (bcol0 + nt*8 + g) * sB + k0 + 2*t);
            uint32_t b1 = *(const uint32_t*)(B + (bcol0 + nt*8 + g) * sB + k0 + 2*t + 8);
            mma16816(acc[nt], a, b0, b1);
        }
    }
}

#define ZACC(A, N) { _Pragma("unroll") for (int _i = 0; _i < (N); _i++) { (A)[_i][0]=0.f;(A)[_i][1]=0.f;(A)[_i][2]=0.f;(A)[_i][3]=0.f; } }

// ================= score / select / pool =================
__global__ void score_kernel(const float* __restrict__ unc) {
    int id = blockIdx.x * blockDim.x + threadIdx.x;
    if (id >= BB * NWIN) return;
    int b = id / NWIN, w = id % NWIN;
    int hy = w >> 6, wx = w & 63;
    const float* base = unc + (size_t)b * HWSZ + (size_t)hy * 8 * WW + wx * 8;
    float s = 0.f;
    #pragma unroll
    for (int iy = 0; iy < 8; iy++)
        #pragma unroll
        for (int ix = 0; ix < 8; ix++) s += base[iy * WW + ix];
    d_score[id] = s * (1.f / 64.f);
}

__global__ void select_kernel() {
    __shared__ unsigned long long key[NWIN];
    int b = blockIdx.x, tid = threadIdx.x;
    for (int i = tid; i < NWIN; i += blockDim.x) {
        unsigned int sb = __float_as_uint(d_score[b * NWIN + i]);
        key[i] = (((unsigned long long)sb) << 12) | (unsigned)(NWIN - 1 - i);
    }
    __syncthreads();
    for (int k = 2; k <= NWIN; k <<= 1)
        for (int j = k >> 1; j > 0; j >>= 1) {
            for (int i = tid; i < NWIN; i += blockDim.x) {
                int ixj = i ^ j;
                if (ixj > i) {
                    unsigned long long a = key[i], c = key[ixj];
                    bool desc = ((i & k) == 0);
                    if (desc ? (a < c) : (a > c)) { key[i] = c; key[ixj] = a; }
                }
            }
            __syncthreads();
        }
    for (int m = tid; m < NWF; m += blockDim.x)
        d_sel[b * NWF + m] = (NWIN - 1) - (int)(key[m] & 0xFFFULL);
}

__global__ void pool_kernel(const float* __restrict__ fm) {
    int bid = blockIdx.x;
    int b = bid >> 13, c = (bid >> 6) & 127, p = bid & 63;
    int p0 = p >> 3, p1 = p & 7;
    const float* base = fm + ((size_t)(b * CC + c) * HH + (size_t)p0 * 64) * WW + p1 * 64;
    float s = 0.f;
    for (int e = threadIdx.x; e < 4096; e += 128) s += base[(e >> 6) * WW + (e & 63)];
    __shared__ float red[128];
    red[threadIdx.x] = s;
    __syncthreads();
    for (int off = 64; off > 0; off >>= 1) {
        if (threadIdx.x < off) red[threadIdx.x] += red[threadIdx.x + off];
        __syncthreads();
    }
    if (threadIdx.x == 0) d_g[(b * 64 + p) * CC + c] = red[0] * (1.f / 4096.f);
}

// global k/v projection -> bf16 (kg row-major, vg transposed)
__global__ void kv2_kernel(const float* __restrict__ kvw) {
    __shared__ float g[64 * 128];
    int b = blockIdx.x, tid = threadIdx.x;
    for (int i = tid; i < 64 * 128; i += 256) g[i] = d_g[b * 64 * 128 + i];
    __syncthreads();
    int which = tid >> 7, c = tid & 127;
    const float* wrow = kvw + (size_t)(which * 128 + c) * 128;
    for (int pg = 0; pg < 8; pg++) {
        float s[8];
        #pragma unroll
        for (int q = 0; q < 8; q++) s[q] = 0.f;
        for (int k = 0; k < 128; k++) {
            float wv = __ldg(&wrow[k]);
            #pragma unroll
            for (int q = 0; q < 8; q++) s[q] = fmaf(g[(pg * 8 + q) * 128 + k], wv, s[q]);
        }
        #pragma unroll
        for (int q = 0; q < 8; q++) {
            int p = pg * 8 + q;
            __nv_bfloat16 h = __float2bfloat16_rn(s[q]);
            if (which) d_vgtb[b][c * 64 + p] = h;
            else       d_kgb [b][p * 128 + c] = h;
        }
    }
}

__global__ void copy_kernel(const float4* __restrict__ in, float4* __restrict__ out, int n4) {
    int stride = gridDim.x * blockDim.x;
    for (int i = blockIdx.x * blockDim.x + threadIdx.x; i < n4; i += stride) out[i] = in[i];
}

// weight loader: tid pair per row; writes hi (and lo) at stride SA
__device__ __forceinline__ void load_w(const float* __restrict__ W, __nv_bfloat16* H,
                                       __nv_bfloat16* L, int tid) {
    int r = tid >> 1, hf = tid & 1;
    const float4* src = (const float4*)(W + (size_t)r * 128 + hf * 64);
    #pragma unroll
    for (int i = 0; i < 16; i++) {
        float4 v = __ldg(&src[i]);
        int c = hf * 64 + i * 4;
        uint32_t h0, l0, h1, l1;
        split2(v.x, v.y, h0, l0);
        split2(v.z, v.w, h1, l1);
        *(uint32_t*)&H[r * SA + c]     = h0;
        *(uint32_t*)&H[r * SA + c + 2] = h1;
        if (L) {
            *(uint32_t*)&L[r * SA + c]     = l0;
            *(uint32_t*)&L[r * SA + c + 2] = l1;
        }
    }
}

// ================= window kernel (HMMA via mma.sync bf16) =================
__global__ __launch_bounds__(256) void window_kernel(
    const float* __restrict__ fm,
    const float* __restrict__ qgw,
    const float* __restrict__ l0w, const float* __restrict__ l0b,
    const float* __restrict__ qkvw,
    const float* __restrict__ pw, const float* __restrict__ pb,
    float* __restrict__ out)
{
    extern __shared__ __align__(16) unsigned char smc[];
    __nv_bfloat16* WFH = (__nv_bfloat16*)(smc + O_A);
    __nv_bfloat16* WFL = (__nv_bfloat16*)(smc + O_B);
    __nv_bfloat16* WTH = (__nv_bfloat16*)(smc + O_C);
    __nv_bfloat16* WTL = (__nv_bfloat16*)(smc + O_D);
    __nv_bfloat16* EB  = (__nv_bfloat16*)(smc + O_E);
    __nv_bfloat16* KG  = (__nv_bfloat16*)(smc + O_F);    // later k2 (full 128 rows)
    __nv_bfloat16* VGT = (__nv_bfloat16*)(smc + O_VGT);
    __nv_bfloat16* PB  = (__nv_bfloat16*)(smc + O_P);
    float* DUMP  = (float*)(smc + O_C);
    float* bias1 = (float*)(smc);
    float* bias2 = (float*)(smc + 512);

    const int tid = threadIdx.x;
    const int w   = tid >> 5, lane = tid & 31;
    const int g   = lane >> 2, t = lane & 3;
    const int row0 = w * 16;
    const int wloc = w >> 2;                 // window of this warp's rows

    const int b  = blockIdx.x / NPAIR;
    const int pr = blockIdx.x % NPAIR;

    // ---- gather + biases + kv copy + qg weights ----
    {
        int rr = tid >> 1, hf = tid & 1;
        int wsel = d_sel[b * NWF + pr * 2 + (rr >> 6)];
        int hy = wsel >> 6, wx = wsel & 63, tk = rr & 63;
        const float* fb = fm + (size_t)b * CC * HWSZ + (size_t)(hy * 8 + (tk >> 3)) * WW + wx * 8 + (tk & 7);
        #pragma unroll 4
        for (int i = 0; i < 64; i += 2) {
            int c = hf * 64 + i;
            float x0 = __ldg(fb + (size_t)c * HWSZ);
            float x1 = __ldg(fb + (size_t)(c + 1) * HWSZ);
            uint32_t h, l; split2(x0, x1, h, l);
            *(uint32_t*)&WFH[rr * SA + c] = h;
            *(uint32_t*)&WFL[rr * SA + c] = l;
        }
        if (tid < 128) { bias1[tid] = l0b[tid]; bias2[tid] = pb[tid]; }
        const uint32_t* sk = (const uint32_t*)d_kgb[b];
        const uint32_t* sv = (const uint32_t*)d_vgtb[b];
        for (int i = tid; i < 4096; i += 256) {
            int p = i >> 6, cp = i & 63;
            *(uint32_t*)&KG[p * SA + cp * 2] = sk[i];
            int c2 = i >> 5, pp = i & 31;
            *(uint32_t*)&VGT[c2 * SP + pp * 2] = sv[i];
        }
        load_w(qgw, WTH, nullptr, tid);
    }
    __syncthreads();

    // ---- wf master in registers ----
    float wma[32], wmb[32];      // rows row0+g, row0+8+g; index nt*2+e -> col 8nt+2t+e
    #pragma unroll
    for (int nt = 0; nt < 16; nt++) {
        int c = 8 * nt + 2 * t;
        float2 h = up2(*(uint32_t*)&WFH[(row0 + g) * SA + c]);
        float2 l = up2(*(uint32_t*)&WFL[(row0 + g) * SA + c]);
        wma[nt*2] = h.x + l.x; wma[nt*2+1] = h.y + l.y;
        float2 h2 = up2(*(uint32_t*)&WFH[(row0 + 8 + g) * SA + c]);
        float2 l2 = up2(*(uint32_t*)&WFL[(row0 + 8 + g) * SA + c]);
        wmb[nt*2] = h2.x + l2.x; wmb[nt*2+1] = h2.y + l2.y;
    }

    float acc[16][4];

#define STORE_BF16(DST, STRIDE) { _Pragma("unroll") for (int nt = 0; nt < 16; nt++) { int c = 8*nt + 2*t; \
    *(uint32_t*)&(DST)[(row0 + g) * (STRIDE) + c]     = pkf(acc[nt][0], acc[nt][1]); \
    *(uint32_t*)&(DST)[(row0 + 8 + g) * (STRIDE) + c] = pkf(acc[nt][2], acc[nt][3]); } }

#define RESPLIT() { _Pragma("unroll") for (int nt = 0; nt < 16; nt++) { int c = 8*nt + 2*t; uint32_t h, l; \
    split2(wma[nt*2], wma[nt*2+1], h, l); \
    *(uint32_t*)&WFH[(row0 + g) * SA + c] = h; *(uint32_t*)&WFL[(row0 + g) * SA + c] = l; \
    split2(wmb[nt*2], wmb[nt*2+1], h, l); \
    *(uint32_t*)&WFH[(row0 + 8 + g) * SA + c] = h; *(uint32_t*)&WFL[(row0 + 8 + g) * SA + c] = l; } }

#define SOFTMAX64(SC) { \
    float mxa = -1e30f, mxb = -1e30f; \
    _Pragma("unroll") for (int nt = 0; nt < 8; nt++) { \
        (SC)[nt][0] *= SCALEF; (SC)[nt][1] *= SCALEF; (SC)[nt][2] *= SCALEF; (SC)[nt][3] *= SCALEF; \
        mxa = fmaxf(mxa, fmaxf((SC)[nt][0], (SC)[nt][1])); \
        mxb = fmaxf(mxb, fmaxf((SC)[nt][2], (SC)[nt][3])); } \
    mxa = fmaxf(mxa, __shfl_xor_sync(0xffffffffu, mxa, 1)); \
    mxa = fmaxf(mxa, __shfl_xor_sync(0xffffffffu, mxa, 2)); \
    mxb = fmaxf(mxb, __shfl_xor_sync(0xffffffffu, mxb, 1)); \
    mxb = fmaxf(mxb, __shfl_xor_sync(0xffffffffu, mxb, 2)); \
    float ea = 0.f, eb = 0.f; \
    _Pragma("unroll") for (int nt = 0; nt < 8; nt++) { \
        (SC)[nt][0] = __expf((SC)[nt][0] - mxa); (SC)[nt][1] = __expf((SC)[nt][1] - mxa); \
        (SC)[nt][2] = __expf((SC)[nt][2] - mxb); (SC)[nt][3] = __expf((SC)[nt][3] - mxb); \
        ea += (SC)[nt][0] + (SC)[nt][1]; eb += (SC)[nt][2] + (SC)[nt][3]; } \
    ea += __shfl_xor_sync(0xffffffffu, ea, 1); ea += __shfl_xor_sync(0xffffffffu, ea, 2); \
    eb += __shfl_xor_sync(0xffffffffu, eb, 1); eb += __shfl_xor_sync(0xffffffffu, eb, 2); \
    float ia = 1.f / ea, ib = 1.f / eb; \
    _Pragma("unroll") for (int nt = 0; nt < 8; nt++) { int c = 8*nt + 2*t; \
        *(uint32_t*)&PB[(row0 + g) * SP + c]     = pkf((SC)[nt][0] * ia, (SC)[nt][1] * ia); \
        *(uint32_t*)&PB[(row0 + 8 + g) * SP + c] = pkf((SC)[nt][2] * ib, (SC)[nt][3] * ib); } }

    // ---- cross attention: q = wf @ Wq^T ----
    ZACC(acc, 16);
    gpass<16, 8>(acc, WFH, SA, row0, WTH, SA, 0, g, t);
    STORE_BF16(EB, SA);
    __syncthreads();

    {   // scores = q @ kg^T (N=64), softmax
        float sc[8][4]; ZACC(sc, 8);
        gpass<8, 8>(sc, EB, SA, row0, KG, SA, 0, g, t);
        SOFTMAX64(sc);
    }
    __syncthreads();

    // AV = P @ vgT^T (K=64, N=128); wf += AV
    ZACC(acc, 16);
    gpass<16, 4>(acc, PB, SP, row0, VGT, SP, 0, g, t);
    #pragma unroll
    for (int nt = 0; nt < 16; nt++) {
        wma[nt*2] += acc[nt][0]; wma[nt*2+1] += acc[nt][1];
        wmb[nt*2] += acc[nt][2]; wmb[nt*2+1] += acc[nt][3];
    }
    RESPLIT();
    __syncthreads();

    // ---- MLP1 (3-pass split) ----
    load_w(l0w, WTH, WTL, tid);
    __syncthreads();
    ZACC(acc, 16);
    gpass<16, 8>(acc, WFH, SA, row0, WTH, SA, 0, g, t);
    gpass<16, 8>(acc, WFH, SA, row0, WTL, SA, 0, g, t);
    gpass<16, 8>(acc, WFL, SA, row0, WTH, SA, 0, g, t);
    #pragma unroll
    for (int nt = 0; nt < 16; nt++) {
        int c = 8 * nt + 2 * t;
        wma[nt*2]   += geluf(acc[nt][0] + bias1[c]);
        wma[nt*2+1] += geluf(acc[nt][1] + bias1[c+1]);
        wmb[nt*2]   += geluf(acc[nt][2] + bias1[c]);
        wmb[nt*2+1] += geluf(acc[nt][3] + bias1[c+1]);
    }
    RESPLIT();
    __syncthreads();

    // ---- self attention ----
    load_w(qkvw, WTH, nullptr, tid);            // Wq2
    __syncthreads();
    ZACC(acc, 16);
    gpass<16, 8>(acc, WFH, SA, row0, WTH, SA, 0, g, t);   // q2
    STORE_BF16(EB, SA);
    __syncthreads();

    load_w(qkvw + 128 * 128, WTH, nullptr, tid); // Wk2
    __syncthreads();
    ZACC(acc, 16);
    gpass<16, 8>(acc, WFH, SA, row0, WTH, SA, 0, g, t);   // k2 -> F (full 128 rows)
    STORE_BF16(KG, SA);
    __syncthreads();

    {   // scores2 = q2 @ k2^T, own 64-col block, softmax
        float sc[8][4]; ZACC(sc, 8);
        gpass<8, 8>(sc, EB, SA, row0, KG, SA, wloc * 64, g, t);
        SOFTMAX64(sc);
    }
    __syncthreads();

    load_w(qkvw + 256 * 128, WTH, nullptr, tid); // Wv2
    __syncthreads();
    ZACC(acc, 16);
    gpass<16, 8>(acc, WTH, SA, row0, WFH, SA, 0, g, t);   // v2T = Wv @ wf^T (rows = channels)
    STORE_BF16(EB, SA);
    __syncthreads();

    // AV2 = P2 @ v2 (K = own 64 tokens)
    ZACC(acc, 16);
    gpass<16, 4>(acc, PB, SP, row0, EB + wloc * 64, SA, 0, g, t);
    __syncthreads();                             // all mma done before DUMP overlays WT
    #pragma unroll
    for (int nt = 0; nt < 16; nt++) {
        int c = 8 * nt + 2 * t;
        *(float2*)&DUMP[(row0 + g) * SD + c]     = make_float2(acc[nt][0], acc[nt][1]);
        *(float2*)&DUMP[(row0 + 8 + g) * SD + c] = make_float2(acc[nt][2], acc[nt][3]);
    }
    __syncthreads();

    {   // quirk: wf[t][j] += av[wloc*64 + j%64][2*(t%64) + j/64]
        int rA = (row0 + g) & 63, rB = (row0 + 8 + g) & 63;
        int base = wloc * 64;
        #pragma unroll
        for (int nt = 0; nt < 16; nt++) {
            #pragma unroll
            for (int e = 0; e < 2; e++) {
                int j = 8 * nt + 2 * t + e;
                int rj = (base + (j & 63)) * SD + (j >> 6);
                wma[nt*2+e] += DUMP[rj + 2 * rA];
                wmb[nt*2+e] += DUMP[rj + 2 * rB];
            }
        }
    }
    RESPLIT();
    __syncthreads();

    // ---- MLP2 (3-pass) + final ----
    load_w(pw, WTH, WTL, tid);
    __syncthreads();
    ZACC(acc, 16);
    gpass<16, 8>(acc, WFH, SA, row0, WTH, SA, 0, g, t);
    gpass<16, 8>(acc, WFH, SA, row0, WTL, SA, 0, g, t);
    gpass<16, 8>(acc, WFL, SA, row0, WTH, SA, 0, g, t);
    #pragma unroll
    for (int nt = 0; nt < 16; nt++) {
        int c = 8 * nt + 2 * t;
        wma[nt*2]   += geluf(acc[nt][0] + bias2[c]);
        wma[nt*2+1] += geluf(acc[nt][1] + bias2[c+1]);
        wmb[nt*2]   += geluf(acc[nt][2] + bias2[c]);
        wmb[nt*2+1] += geluf(acc[nt][3] + bias2[c+1]);
    }
    __syncthreads();                             // all MLP2 mma done before DUMP overlays WT
    #pragma unroll
    for (int nt = 0; nt < 16; nt++) {
        int c = 8 * nt + 2 * t;
        *(float2*)&DUMP[(row0 + g) * SD + c]     = make_float2(wma[nt*2], wma[nt*2+1]);
        *(float2*)&DUMP[(row0 + 8 + g) * SD + c] = make_float2(wmb[nt*2], wmb[nt*2+1]);
    }
    __syncthreads();

    {   // scatter
        int rr = tid >> 1, hf = tid & 1;
        int wsel = d_sel[b * NWF + pr * 2 + (rr >> 6)];
        int hy = wsel >> 6, wx = wsel & 63, tk = rr & 63;
        float* ob = out + (size_t)b * CC * HWSZ + (size_t)(hy * 8 + (tk >> 3)) * WW + wx * 8 + (tk & 7);
        #pragma unroll 8
        for (int i = 0; i < 64; i++) {
            int c = hf * 64 + i;
            ob[(size_t)c * HWSZ] = DUMP[rr * SD + c];
        }
    }
#undef STORE_BF16
#undef RESPLIT
#undef SOFTMAX64
}

// =====================================================================
extern "C" void kernel_launch(void* const* d_in, const int* in_sizes, int n_in,
                              void* d_out, int out_size) {
    const float* fm   = (const float*)d_in[0];
    const float* unc  = (const float*)d_in[1];
    const float* qgw  = (const float*)d_in[2];
    const float* kvw  = (const float*)d_in[3];
    const float* l0w  = (const float*)d_in[4];
    const float* l0b  = (const float*)d_in[5];
    const float* qkvw = (const float*)d_in[6];
    const float* pw   = (const float*)d_in[7];
    const float* pb   = (const float*)d_in[8];
    float* out = (float*)d_out;

    cudaFuncSetAttribute(window_kernel, cudaFuncAttributeMaxDynamicSharedMemorySize, SMEM_SZ);

    score_kernel<<<(BB * NWIN + 255) / 256, 256>>>(unc);
    select_kernel<<<BB, 1024>>>();
    pool_kernel<<<BB * CC * 64, 128>>>(fm);
    kv2_kernel<<<BB, 256>>>(kvw);

    int n4 = BB * CC * HH * WW / 4;
    copy_kernel<<<8192, 256>>>((const float4*)fm, (float4*)out, n4);

    window_kernel<<<BB * NPAIR, 256, SMEM_SZ>>>(fm, qgw, l0w, l0b, qkvw, pw, pb, out);
}

// round 5
// speedup vs baseline: 2.9247x; 1.7807x over previous
#include <cuda_runtime.h>
#include <cuda_bf16.h>
#include <math.h>
#include <stdint.h>

#define BB   2
#define CC   128
#define HH   512
#define WW   512
#define NWIN 4096
#define NWF  1228
#define NPAIR (NWF/2)
#define HWSZ ((size_t)HH*(size_t)WW)
#define SCALEF 0.08838834764831845f

// strides (elements)
#define SA 136
#define SP 72
#define SD 132

// smem byte offsets
#define O_A   1024
#define O_B   35840
#define O_C   70656             // WTH (DUMP overlays C+D)
#define O_D   105472            // WTL
#define O_E   140288            // q / q2 / v2T
#define O_F   175104            // kg (64 rows) then k2 (128 rows, spills into VGT region: dead)
#define O_VGT (O_F+17408)
#define O_P   210944            // P 128x72 bf16
#define SMEM_SZ 229376

// -------- device scratch --------
__device__ float d_score[BB * NWIN];
__device__ int   d_sel[BB * NWF];
__device__ unsigned d_selmask[BB * 128];
__device__ float d_g[BB * 64 * CC];
__device__ __nv_bfloat16 d_kgb[BB][64 * 128];
__device__ __nv_bfloat16 d_vgtb[BB][128 * 64];

// ---------------- helpers ----------------
__device__ __forceinline__ uint32_t pkf(float a, float b){
    __nv_bfloat162 t = __floats2bfloat162_rn(a, b);
    return *reinterpret_cast<uint32_t*>(&t);
}
__device__ __forceinline__ float2 up2(uint32_t u){
    __nv_bfloat162 b = *reinterpret_cast<__nv_bfloat162*>(&u);
    return make_float2(__bfloat162float(b.x), __bfloat162float(b.y));
}
__device__ __forceinline__ void split2(float x0, float x1, uint32_t& h, uint32_t& l){
    __nv_bfloat16 b0 = __float2bfloat16_rn(x0), b1 = __float2bfloat16_rn(x1);
    __nv_bfloat162 hb; hb.x = b0; hb.y = b1;
    h = *reinterpret_cast<uint32_t*>(&hb);
    l = pkf(x0 - __bfloat162float(b0), x1 - __bfloat162float(b1));
}
__device__ __forceinline__ float geluf(float x){
    return 0.5f * x * (1.f + erff(x * 0.70710678118654752f));
}
__device__ __forceinline__ void mma16816(float* d, const uint32_t* a, uint32_t b0, uint32_t b1){
    asm("mma.sync.aligned.m16n8k16.row.col.f32.bf16.bf16.f32 "
        "{%0,%1,%2,%3},{%4,%5,%6,%7},{%8,%9},{%0,%1,%2,%3};"
        : "+f"(d[0]), "+f"(d[1]), "+f"(d[2]), "+f"(d[3])
        : "r"(a[0]), "r"(a[1]), "r"(a[2]), "r"(a[3]), "r"(b0), "r"(b1));
}

template<int NT, int KS>
__device__ __forceinline__ void gpass(float (*acc)[4],
                                      const __nv_bfloat16* A, int sA, int row0,
                                      const __nv_bfloat16* B, int sB, int bcol0,
                                      int g, int t){
    #pragma unroll
    for (int ks = 0; ks < KS; ks++){
        const int k0 = ks * 16;
        uint32_t a[4];
        a[0] = *(const uint32_t*)(A + (row0 + g)     * sA + k0 + 2*t);
        a[1] = *(const uint32_t*)(A + (row0 + 8 + g) * sA + k0 + 2*t);
        a[2] = *(const uint32_t*)(A + (row0 + g)     * sA + k0 + 2*t + 8);
        a[3] = *(const uint32_t*)(A + (row0 + 8 + g) * sA + k0 + 2*t + 8);
        #pragma unroll
        for (int nt = 0; nt < NT; nt++){
            uint32_t b0 = *(const uint32_t*)(B + (bcol0 + nt*8 + g) * sB + k0 + 2*t);
            uint32_t b1 = *(const uint32_t*)(B + (bcol0 + nt*8 + g) * sB + k0 + 2*t + 8);
            mma16816(acc[nt], a, b0, b1);
        }
    }
}

#define ZACC(A, N) { _Pragma("unroll") for (int _i = 0; _i < (N); _i++) { (A)[_i][0]=0.f;(A)[_i][1]=0.f;(A)[_i][2]=0.f;(A)[_i][3]=0.f; } }

// ================= score =================
__global__ void score_kernel(const float* __restrict__ unc) {
    int id = blockIdx.x * blockDim.x + threadIdx.x;
    if (id >= BB * NWIN) return;
    int b = id / NWIN, w = id % NWIN;
    int hy = w >> 6, wx = w & 63;
    const float* base = unc + (size_t)b * HWSZ + (size_t)hy * 8 * WW + wx * 8;
    float s = 0.f;
    #pragma unroll
    for (int iy = 0; iy < 8; iy++)
        #pragma unroll
        for (int ix = 0; ix < 8; ix++) s += base[iy * WW + ix];
    d_score[id] = s * (1.f / 64.f);
}

// ================= selection =================
__global__ void select_kernel() {
    __shared__ unsigned long long key[NWIN];
    int b = blockIdx.x, tid = threadIdx.x;
    for (int i = tid; i < 128; i += blockDim.x) d_selmask[b * 128 + i] = 0;
    for (int i = tid; i < NWIN; i += blockDim.x) {
        unsigned int sb = __float_as_uint(d_score[b * NWIN + i]);
        key[i] = (((unsigned long long)sb) << 12) | (unsigned)(NWIN - 1 - i);
    }
    __syncthreads();
    for (int k = 2; k <= NWIN; k <<= 1)
        for (int j = k >> 1; j > 0; j >>= 1) {
            for (int i = tid; i < NWIN; i += blockDim.x) {
                int ixj = i ^ j;
                if (ixj > i) {
                    unsigned long long a = key[i], c = key[ixj];
                    bool desc = ((i & k) == 0);
                    if (desc ? (a < c) : (a > c)) { key[i] = c; key[ixj] = a; }
                }
            }
            __syncthreads();
        }
    for (int m = tid; m < NWF; m += blockDim.x) {
        int idx = (NWIN - 1) - (int)(key[m] & 0xFFFULL);
        d_sel[b * NWF + m] = idx;
        atomicOr(&d_selmask[b * 128 + (idx >> 5)], 1u << (idx & 31));
    }
}

// ============ fused pool + selective copy ============
__global__ void poolcopy_kernel(const float* __restrict__ fm, float* __restrict__ out) {
    int bid = blockIdx.x;                // BB*CC*64
    int b = bid >> 13, c = (bid >> 6) & 127, p = bid & 63;
    int p0 = p >> 3, p1 = p & 7;
    __shared__ float red[128];
    __shared__ unsigned char wsel[64];
    int tid = threadIdx.x;
    if (tid < 64) {
        int wy = p0 * 8 + (tid >> 3), wx = p1 * 8 + (tid & 7);
        int wdw = wy * 64 + wx;
        wsel[tid] = (d_selmask[b * 128 + (wdw >> 5)] >> (wdw & 31)) & 1;
    }
    __syncthreads();
    size_t base_off = ((size_t)(b * CC + c) * HH + (size_t)p0 * 64) * WW + p1 * 64;
    const float* base = fm + base_off;
    float* ob = out + base_off;
    float s = 0.f;
    for (int e4 = tid; e4 < 1024; e4 += 128) {
        int r = e4 >> 4, col4 = (e4 & 15) * 4;
        float4 v = *(const float4*)(base + (size_t)r * WW + col4);
        s += (v.x + v.y) + (v.z + v.w);
        if (!wsel[(r >> 3) * 8 + (col4 >> 3)])
            *(float4*)(ob + (size_t)r * WW + col4) = v;
    }
    red[tid] = s;
    __syncthreads();
    for (int off = 64; off > 0; off >>= 1) {
        if (tid < off) red[tid] += red[tid + off];
        __syncthreads();
    }
    if (tid == 0) d_g[(b * 64 + p) * CC + c] = red[0] * (1.f / 4096.f);
}

// ============ global k/v projection (parallel) ============
__global__ void kv2_kernel(const float* __restrict__ kvw) {
    __shared__ float g[64 * 128];
    __shared__ float wt[32 * 129];
    int bid = blockIdx.x;                // BB*2*4 = 16
    int b = bid >> 3, which = (bid >> 2) & 1, cg = bid & 3;
    int tid = threadIdx.x;               // 256
    for (int i = tid; i < 64 * 128; i += 256) g[i] = d_g[b * 64 * 128 + i];
    const float* wb = kvw + ((size_t)(which * 128 + cg * 32)) * 128;
    for (int i = tid; i < 32 * 128; i += 256) wt[(i >> 7) * 129 + (i & 127)] = wb[i];
    __syncthreads();
    int cl = tid & 31, c = cg * 32 + cl;
    int pb = (tid >> 5) * 8;
    float s[8] = {0.f,0.f,0.f,0.f,0.f,0.f,0.f,0.f};
    for (int k = 0; k < 128; k++) {
        float wv = wt[cl * 129 + k];
        #pragma unroll
        for (int q = 0; q < 8; q++) s[q] = fmaf(g[(pb + q) * 128 + k], wv, s[q]);
    }
    #pragma unroll
    for (int q = 0; q < 8; q++) {
        int p = pb + q;
        __nv_bfloat16 h = __float2bfloat16_rn(s[q]);
        if (which) d_vgtb[b][c * 64 + p] = h;
        else       d_kgb [b][p * 128 + c] = h;
    }
}

// weight loader, 256-thread variant (2 threads/row)
__device__ __forceinline__ void load_w(const float* __restrict__ W, __nv_bfloat16* H,
                                       __nv_bfloat16* L, int tid) {
    int r = tid >> 1, hf = tid & 1;
    const float4* src = (const float4*)(W + (size_t)r * 128 + hf * 64);
    #pragma unroll
    for (int i = 0; i < 16; i++) {
        float4 v = __ldg(&src[i]);
        int c = hf * 64 + i * 4;
        uint32_t h0, l0, h1, l1;
        split2(v.x, v.y, h0, l0);
        split2(v.z, v.w, h1, l1);
        *(uint32_t*)&H[r * SA + c]     = h0;
        *(uint32_t*)&H[r * SA + c + 2] = h1;
        if (L) {
            *(uint32_t*)&L[r * SA + c]     = l0;
            *(uint32_t*)&L[r * SA + c + 2] = l1;
        }
    }
}
// weight loader, 512-thread variant (4 threads/row)
__device__ __forceinline__ void load_w4(const float* __restrict__ W, __nv_bfloat16* H,
                                        __nv_bfloat16* L, int tid) {
    int r = tid >> 2, q = tid & 3;
    const float4* src = (const float4*)(W + (size_t)r * 128 + q * 32);
    #pragma unroll
    for (int i = 0; i < 8; i++) {
        float4 v = __ldg(&src[i]);
        int c = q * 32 + i * 4;
        uint32_t h0, l0, h1, l1;
        split2(v.x, v.y, h0, l0);
        split2(v.z, v.w, h1, l1);
        *(uint32_t*)&H[r * SA + c]     = h0;
        *(uint32_t*)&H[r * SA + c + 2] = h1;
        if (L) {
            *(uint32_t*)&L[r * SA + c]     = l0;
            *(uint32_t*)&L[r * SA + c + 2] = l1;
        }
    }
}

// ================= window kernel (512 threads, 2 warps per row-block) =================
__global__ __launch_bounds__(512) void window_kernel(
    const float* __restrict__ fm,
    const float* __restrict__ qgw,
    const float* __restrict__ l0w, const float* __restrict__ l0b,
    const float* __restrict__ qkvw,
    const float* __restrict__ pw, const float* __restrict__ pb,
    float* __restrict__ out)
{
    extern __shared__ __align__(16) unsigned char smc[];
    __nv_bfloat16* WFH = (__nv_bfloat16*)(smc + O_A);
    __nv_bfloat16* WFL = (__nv_bfloat16*)(smc + O_B);
    __nv_bfloat16* WTH = (__nv_bfloat16*)(smc + O_C);
    __nv_bfloat16* WTL = (__nv_bfloat16*)(smc + O_D);
    __nv_bfloat16* EB  = (__nv_bfloat16*)(smc + O_E);
    __nv_bfloat16* KG  = (__nv_bfloat16*)(smc + O_F);
    __nv_bfloat16* VGT = (__nv_bfloat16*)(smc + O_VGT);
    __nv_bfloat16* PB  = (__nv_bfloat16*)(smc + O_P);
    float* DUMP  = (float*)(smc + O_C);
    float* bias1 = (float*)(smc);
    float* bias2 = (float*)(smc + 512);

    const int tid  = threadIdx.x;
    const int w    = tid >> 5, lane = tid & 31;
    const int g    = lane >> 2, t = lane & 3;
    const int rb   = w & 7;            // row block
    const int row0 = rb * 16;
    const int nh   = w >> 3;           // N half
    const int cb   = nh * 64;          // col base
    const int wloc = rb >> 2;          // window of these rows

    const int b  = blockIdx.x / NPAIR;
    const int pr = blockIdx.x % NPAIR;

    // ---- P0: gather + biases + kv images + qg weights ----
    {
        int rr = tid >> 2, q4 = tid & 3;
        int wsel = d_sel[b * NWF + pr * 2 + (rr >> 6)];
        int hy = wsel >> 6, wx = wsel & 63, tk = rr & 63;
        const float* fb = fm + (size_t)b * CC * HWSZ + (size_t)(hy * 8 + (tk >> 3)) * WW + wx * 8 + (tk & 7);
        #pragma unroll 4
        for (int i = 0; i < 32; i += 2) {
            int c = q4 * 32 + i;
            float x0 = __ldg(fb + (size_t)c * HWSZ);
            float x1 = __ldg(fb + (size_t)(c + 1) * HWSZ);
            uint32_t h, l; split2(x0, x1, h, l);
            *(uint32_t*)&WFH[rr * SA + c] = h;
            *(uint32_t*)&WFL[rr * SA + c] = l;
        }
        if (tid < 128) { bias1[tid] = l0b[tid]; bias2[tid] = pb[tid]; }
        const uint32_t* sk = (const uint32_t*)d_kgb[b];
        const uint32_t* sv = (const uint32_t*)d_vgtb[b];
        for (int i = tid; i < 4096; i += 512) {
            int p = i >> 6, cp = i & 63;
            *(uint32_t*)&KG[p * SA + cp * 2] = sk[i];
            int c2 = i >> 5, pp = i & 31;
            *(uint32_t*)&VGT[c2 * SP + pp * 2] = sv[i];
        }
        load_w4(qgw, WTH, nullptr, tid);
    }
    __syncthreads();

    // wf master in registers: rows row0+g / row0+8+g, cols cb + 8nt + 2t (+e)
    float wma[16], wmb[16];
    #pragma unroll
    for (int nt = 0; nt < 8; nt++) {
        int c = cb + 8 * nt + 2 * t;
        float2 h = up2(*(uint32_t*)&WFH[(row0 + g) * SA + c]);
        float2 l = up2(*(uint32_t*)&WFL[(row0 + g) * SA + c]);
        wma[nt*2] = h.x + l.x; wma[nt*2+1] = h.y + l.y;
        float2 h2 = up2(*(uint32_t*)&WFH[(row0 + 8 + g) * SA + c]);
        float2 l2 = up2(*(uint32_t*)&WFL[(row0 + 8 + g) * SA + c]);
        wmb[nt*2] = h2.x + l2.x; wmb[nt*2+1] = h2.y + l2.y;
    }

    float acc[8][4];

#define STORE8(DST, STRIDE) { _Pragma("unroll") for (int nt = 0; nt < 8; nt++) { int c = cb + 8*nt + 2*t; \
    *(uint32_t*)&(DST)[(row0 + g) * (STRIDE) + c]     = pkf(acc[nt][0], acc[nt][1]); \
    *(uint32_t*)&(DST)[(row0 + 8 + g) * (STRIDE) + c] = pkf(acc[nt][2], acc[nt][3]); } }

#define RESPLIT8() { _Pragma("unroll") for (int nt = 0; nt < 8; nt++) { int c = cb + 8*nt + 2*t; uint32_t h, l; \
    split2(wma[nt*2], wma[nt*2+1], h, l); \
    *(uint32_t*)&WFH[(row0 + g) * SA + c] = h; *(uint32_t*)&WFL[(row0 + g) * SA + c] = l; \
    split2(wmb[nt*2], wmb[nt*2+1], h, l); \
    *(uint32_t*)&WFH[(row0 + 8 + g) * SA + c] = h; *(uint32_t*)&WFL[(row0 + 8 + g) * SA + c] = l; } }

#define SOFTMAX64(SC) { \
    float mxa = -1e30f, mxb = -1e30f; \
    _Pragma("unroll") for (int nt = 0; nt < 8; nt++) { \
        (SC)[nt][0] *= SCALEF; (SC)[nt][1] *= SCALEF; (SC)[nt][2] *= SCALEF; (SC)[nt][3] *= SCALEF; \
        mxa = fmaxf(mxa, fmaxf((SC)[nt][0], (SC)[nt][1])); \
        mxb = fmaxf(mxb, fmaxf((SC)[nt][2], (SC)[nt][3])); } \
    mxa = fmaxf(mxa, __shfl_xor_sync(0xffffffffu, mxa, 1)); \
    mxa = fmaxf(mxa, __shfl_xor_sync(0xffffffffu, mxa, 2)); \
    mxb = fmaxf(mxb, __shfl_xor_sync(0xffffffffu, mxb, 1)); \
    mxb = fmaxf(mxb, __shfl_xor_sync(0xffffffffu, mxb, 2)); \
    float ea = 0.f, eb = 0.f; \
    _Pragma("unroll") for (int nt = 0; nt < 8; nt++) { \
        (SC)[nt][0] = __expf((SC)[nt][0] - mxa); (SC)[nt][1] = __expf((SC)[nt][1] - mxa); \
        (SC)[nt][2] = __expf((SC)[nt][2] - mxb); (SC)[nt][3] = __expf((SC)[nt][3] - mxb); \
        ea += (SC)[nt][0] + (SC)[nt][1]; eb += (SC)[nt][2] + (SC)[nt][3]; } \
    ea += __shfl_xor_sync(0xffffffffu, ea, 1); ea += __shfl_xor_sync(0xffffffffu, ea, 2); \
    eb += __shfl_xor_sync(0xffffffffu, eb, 1); eb += __shfl_xor_sync(0xffffffffu, eb, 2); \
    float ia = 1.f / ea, ib = 1.f / eb; \
    _Pragma("unroll") for (int nt = 0; nt < 8; nt++) { int c = 8*nt + 2*t; \
        *(uint32_t*)&PB[(row0 + g) * SP + c]     = pkf((SC)[nt][0] * ia, (SC)[nt][1] * ia); \
        *(uint32_t*)&PB[(row0 + 8 + g) * SP + c] = pkf((SC)[nt][2] * ib, (SC)[nt][3] * ib); } }

    // ---- P1: q = wf @ Wq_g^T ----
    ZACC(acc, 8);
    gpass<8, 8>(acc, WFH, SA, row0, WTH, SA, cb, g, t);
    STORE8(EB, SA);
    __syncthreads();

    // ---- P2: scoresX + softmax (nh0) | load l0w (nh1) ----
    if (nh == 0) {
        float sc[8][4]; ZACC(sc, 8);
        gpass<8, 8>(sc, EB, SA, row0, KG, SA, 0, g, t);
        SOFTMAX64(sc);
    } else {
        load_w(l0w, WTH, WTL, tid - 256);
    }
    __syncthreads();

    // ---- P3: AV = P @ vgT^T ; wf += AV ----
    ZACC(acc, 8);
    gpass<8, 4>(acc, PB, SP, row0, VGT, SP, cb, g, t);
    #pragma unroll
    for (int nt = 0; nt < 8; nt++) {
        wma[nt*2] += acc[nt][0]; wma[nt*2+1] += acc[nt][1];
        wmb[nt*2] += acc[nt][2]; wmb[nt*2+1] += acc[nt][3];
    }
    RESPLIT8();                 // nobody reads WFH/WFL in this phase
    __syncthreads();

    // ---- P4: MLP1 (3-pass split) ----
    ZACC(acc, 8);
    gpass<8, 8>(acc, WFH, SA, row0, WTH, SA, cb, g, t);
    gpass<8, 8>(acc, WFH, SA, row0, WTL, SA, cb, g, t);
    gpass<8, 8>(acc, WFL, SA, row0, WTH, SA, cb, g, t);
    #pragma unroll
    for (int nt = 0; nt < 8; nt++) {
        int c = cb + 8 * nt + 2 * t;
        wma[nt*2]   += geluf(acc[nt][0] + bias1[c]);
        wma[nt*2+1] += geluf(acc[nt][1] + bias1[c+1]);
        wmb[nt*2]   += geluf(acc[nt][2] + bias1[c]);
        wmb[nt*2+1] += geluf(acc[nt][3] + bias1[c+1]);
    }
    __syncthreads();            // all k-reads of WFH/WFL done before resplit (halves share rows)
    RESPLIT8();
    __syncthreads();

    // ---- P5: load Wq2 ----
    load_w4(qkvw, WTH, nullptr, tid);
    __syncthreads();

    // ---- P6: q2 ----
    ZACC(acc, 8);
    gpass<8, 8>(acc, WFH, SA, row0, WTH, SA, cb, g, t);
    STORE8(EB, SA);
    __syncthreads();

    // ---- P7: load Wk2 into WTL ----
    load_w4(qkvw + 128 * 128, WTL, nullptr, tid);
    __syncthreads();

    // ---- P8: k2 ----
    ZACC(acc, 8);
    gpass<8, 8>(acc, WFH, SA, row0, WTL, SA, cb, g, t);
    STORE8(KG, SA);
    __syncthreads();

    // ---- P9: scores2 + softmax (nh0) | load Wv2 (nh1) ----
    if (nh == 0) {
        float sc[8][4]; ZACC(sc, 8);
        gpass<8, 8>(sc, EB, SA, row0, KG, SA, wloc * 64, g, t);
        SOFTMAX64(sc);
    } else {
        load_w(qkvw + 256 * 128, WTH, nullptr, tid - 256);
    }
    __syncthreads();

    // ---- P10: v2T = Wv @ wf^T ----
    ZACC(acc, 8);
    gpass<8, 8>(acc, WTH, SA, row0, WFH, SA, cb, g, t);
    STORE8(EB, SA);
    __syncthreads();

    // ---- P11: AV2 = P2 @ v2 ----
    ZACC(acc, 8);
    gpass<8, 4>(acc, PB, SP, row0, EB + wloc * 64, SA, cb, g, t);
    __syncthreads();            // all mma done before DUMP overlays WT region
    #pragma unroll
    for (int nt = 0; nt < 8; nt++) {
        int c = cb + 8 * nt + 2 * t;
        *(float2*)&DUMP[(row0 + g) * SD + c]     = make_float2(acc[nt][0], acc[nt][1]);
        *(float2*)&DUMP[(row0 + 8 + g) * SD + c] = make_float2(acc[nt][2], acc[nt][3]);
    }
    __syncthreads();

    // ---- P12: quirk: wf[t][j] += av[wloc*64 + j%64][2*(t%64) + j/64] ----
    {
        int rA = (row0 + g) & 63, rB = (row0 + 8 + g) & 63;
        int base = wloc * 64;
        #pragma unroll
        for (int nt = 0; nt < 8; nt++) {
            #pragma unroll
            for (int e = 0; e < 2; e++) {
                int j = cb + 8 * nt + 2 * t + e;
                int rj = (base + (j & 63)) * SD + (j >> 6);
                wma[nt*2+e] += DUMP[rj + 2 * rA];
                wmb[nt*2+e] += DUMP[rj + 2 * rB];
            }
        }
    }
    RESPLIT8();                 // no WFH readers this phase
    __syncthreads();            // DUMP reads done before pw overwrites

    // ---- P13: load pw ----
    load_w4(pw, WTH, WTL, tid);
    __syncthreads();

    // ---- P14: MLP2 (3-pass) ----
    ZACC(acc, 8);
    gpass<8, 8>(acc, WFH, SA, row0, WTH, SA, cb, g, t);
    gpass<8, 8>(acc, WFH, SA, row0, WTL, SA, cb, g, t);
    gpass<8, 8>(acc, WFL, SA, row0, WTH, SA, cb, g, t);
    #pragma unroll
    for (int nt = 0; nt < 8; nt++) {
        int c = cb + 8 * nt + 2 * t;
        wma[nt*2]   += geluf(acc[nt][0] + bias2[c]);
        wma[nt*2+1] += geluf(acc[nt][1] + bias2[c+1]);
        wmb[nt*2]   += geluf(acc[nt][2] + bias2[c]);
        wmb[nt*2+1] += geluf(acc[nt][3] + bias2[c+1]);
    }
    __syncthreads();            // all mma done before DUMP overlays WT
    #pragma unroll
    for (int nt = 0; nt < 8; nt++) {
        int c = cb + 8 * nt + 2 * t;
        *(float2*)&DUMP[(row0 + g) * SD + c]     = make_float2(wma[nt*2], wma[nt*2+1]);
        *(float2*)&DUMP[(row0 + 8 + g) * SD + c] = make_float2(wmb[nt*2], wmb[nt*2+1]);
    }
    __syncthreads();

    // ---- P15: scatter ----
    {
        int rr = tid >> 2, q4 = tid & 3;
        int wsel = d_sel[b * NWF + pr * 2 + (rr >> 6)];
        int hy = wsel >> 6, wx = wsel & 63, tk = rr & 63;
        float* ob = out + (size_t)b * CC * HWSZ + (size_t)(hy * 8 + (tk >> 3)) * WW + wx * 8 + (tk & 7);
        #pragma unroll 8
        for (int i = 0; i < 32; i++) {
            int c = q4 * 32 + i;
            ob[(size_t)c * HWSZ] = DUMP[rr * SD + c];
        }
    }
#undef STORE8
#undef RESPLIT8
#undef SOFTMAX64
}

// =====================================================================
extern "C" void kernel_launch(void* const* d_in, const int* in_sizes, int n_in,
                              void* d_out, int out_size) {
    const float* fm   = (const float*)d_in[0];
    const float* unc  = (const float*)d_in[1];
    const float* qgw  = (const float*)d_in[2];
    const float* kvw  = (const float*)d_in[3];
    const float* l0w  = (const float*)d_in[4];
    const float* l0b  = (const float*)d_in[5];
    const float* qkvw = (const float*)d_in[6];
    const float* pw   = (const float*)d_in[7];
    const float* pb   = (const float*)d_in[8];
    float* out = (float*)d_out;

    cudaFuncSetAttribute(window_kernel, cudaFuncAttributeMaxDynamicSharedMemorySize, SMEM_SZ);

    score_kernel<<<(BB * NWIN + 255) / 256, 256>>>(unc);
    select_kernel<<<BB, 1024>>>();
    poolcopy_kernel<<<BB * CC * 64, 128>>>(fm, out);
    kv2_kernel<<<16, 256>>>(kvw);
    window_kernel<<<BB * NPAIR, 512, SMEM_SZ>>>(fm, qgw, l0w, l0b, qkvw, pw, pb, out);
}

// round 6
// speedup vs baseline: 3.1261x; 1.0689x over previous
#include <cuda_runtime.h>
#include <cuda_bf16.h>
#include <math.h>
#include <stdint.h>

#define BB   2
#define CC   128
#define HH   512
#define WW   512
#define NWIN 4096
#define NWF  1228
#define NPAIR (NWF/2)
#define HWSZ ((size_t)HH*(size_t)WW)
#define SCALEF 0.08838834764831845f

// strides (elements)
#define SA 136
#define SP 72
#define SD 132

// smem byte offsets
#define O_A   1024              // WFH 128x136 bf16
#define O_B   35840             // WFL
#define O_C   70656             // WTH
#define O_D   105472            // WTL
#define O_E   140288            // EB: q/q2/v2T ; DUMP overlays E..(E+67584)
#define O_F   175104            // KG: kg (64 rows) / k2 (128 rows, spills into VGT: dead)
#define O_VGT (O_F+17408)
#define O_P   210944            // PB 128x72 bf16
#define SMEM_SZ 229376

// -------- device scratch --------
__device__ int   d_sel[BB * NWF];
__device__ unsigned d_selmask[BB * 128];
__device__ float d_g[BB * 64 * CC];
__device__ __nv_bfloat16 d_kgb[BB][64 * 128];
__device__ __nv_bfloat16 d_vgtb[BB][128 * 64];
// weight images: 0=qg 1=l0 2=q2 3=k2 4=v2 5=pw ; lo: 0=l0 1=pw
__device__ __nv_bfloat16 d_whi[6][128 * 128];
__device__ __nv_bfloat16 d_wlo[2][128 * 128];

// ---------------- helpers ----------------
__device__ __forceinline__ uint32_t pkf(float a, float b){
    __nv_bfloat162 t = __floats2bfloat162_rn(a, b);
    return *reinterpret_cast<uint32_t*>(&t);
}
__device__ __forceinline__ float2 up2(uint32_t u){
    __nv_bfloat162 b = *reinterpret_cast<__nv_bfloat162*>(&u);
    return make_float2(__bfloat162float(b.x), __bfloat162float(b.y));
}
__device__ __forceinline__ void split2(float x0, float x1, uint32_t& h, uint32_t& l){
    __nv_bfloat16 b0 = __float2bfloat16_rn(x0), b1 = __float2bfloat16_rn(x1);
    __nv_bfloat162 hb; hb.x = b0; hb.y = b1;
    h = *reinterpret_cast<uint32_t*>(&hb);
    l = pkf(x0 - __bfloat162float(b0), x1 - __bfloat162float(b1));
}
__device__ __forceinline__ float geluf(float x){
    return 0.5f * x * (1.f + erff(x * 0.70710678118654752f));
}
__device__ __forceinline__ void mma16816(float* d, const uint32_t* a, uint32_t b0, uint32_t b1){
    asm("mma.sync.aligned.m16n8k16.row.col.f32.bf16.bf16.f32 "
        "{%0,%1,%2,%3},{%4,%5,%6,%7},{%8,%9},{%0,%1,%2,%3};"
        : "+f"(d[0]), "+f"(d[1]), "+f"(d[2]), "+f"(d[3])
        : "r"(a[0]), "r"(a[1]), "r"(a[2]), "r"(a[3]), "r"(b0), "r"(b1));
}

template<int NT, int KS>
__device__ __forceinline__ void gpass(float (*acc)[4],
                                      const __nv_bfloat16* A, int sA, int row0,
                                      const __nv_bfloat16* B, int sB, int bcol0,
                                      int g, int t){
    #pragma unroll
    for (int ks = 0; ks < KS; ks++){
        const int k0 = ks * 16;
        uint32_t a[4];
        a[0] = *(const uint32_t*)(A + (row0 + g)     * sA + k0 + 2*t);
        a[1] = *(const uint32_t*)(A + (row0 + 8 + g) * sA + k0 + 2*t);
        a[2] = *(const uint32_t*)(A + (row0 + g)     * sA + k0 + 2*t + 8);
        a[3] = *(const uint32_t*)(A + (row0 + 8 + g) * sA + k0 + 2*t + 8);
        #pragma unroll
        for (int nt = 0; nt < NT; nt++){
            uint32_t b0 = *(const uint32_t*)(B + (bcol0 + nt*8 + g) * sB + k0 + 2*t);
            uint32_t b1 = *(const uint32_t*)(B + (bcol0 + nt*8 + g) * sB + k0 + 2*t + 8);
            mma16816(acc[nt], a, b0, b1);
        }
    }
}

#define ZACC(A, N) { _Pragma("unroll") for (int _i = 0; _i < (N); _i++) { (A)[_i][0]=0.f;(A)[_i][1]=0.f;(A)[_i][2]=0.f;(A)[_i][3]=0.f; } }

// ============ selection (+score) + weight prep (spare blocks) ============
__global__ void select_prep_kernel(const float* __restrict__ unc,
                                   const float* __restrict__ qgw,
                                   const float* __restrict__ l0w,
                                   const float* __restrict__ qkvw,
                                   const float* __restrict__ pw) {
    int tid = threadIdx.x;
    if (blockIdx.x >= BB) {
        // weight conversion blocks
        int m = blockIdx.x - BB;
        const float* src = (m == 0) ? qgw : (m == 1) ? l0w :
                           (m < 5) ? qkvw + (size_t)(m - 2) * 16384 : pw;
        bool has_lo = (m == 1) || (m == 5);
        int li = (m == 1) ? 0 : 1;
        for (int i = tid; i < 16384; i += 1024) {
            float x = __ldg(&src[i]);
            __nv_bfloat16 h = __float2bfloat16_rn(x);
            d_whi[m][i] = h;
            if (has_lo) d_wlo[li][i] = __float2bfloat16_rn(x - __bfloat162float(h));
        }
        return;
    }
    __shared__ unsigned long long key[NWIN];
    int b = blockIdx.x;
    for (int i = tid; i < 128; i += blockDim.x) d_selmask[b * 128 + i] = 0;
    for (int i = tid; i < NWIN; i += blockDim.x) {
        int hy = i >> 6, wx = i & 63;
        const float* base = unc + (size_t)b * HWSZ + (size_t)hy * 8 * WW + wx * 8;
        float s = 0.f;
        #pragma unroll
        for (int iy = 0; iy < 8; iy++)
            #pragma unroll
            for (int ix = 0; ix < 8; ix++) s += base[iy * WW + ix];
        unsigned int sb = __float_as_uint(s * (1.f / 64.f));
        key[i] = (((unsigned long long)sb) << 12) | (unsigned)(NWIN - 1 - i);
    }
    __syncthreads();
    for (int k = 2; k <= NWIN; k <<= 1)
        for (int j = k >> 1; j > 0; j >>= 1) {
            for (int i = tid; i < NWIN; i += blockDim.x) {
                int ixj = i ^ j;
                if (ixj > i) {
                    unsigned long long a = key[i], c = key[ixj];
                    bool desc = ((i & k) == 0);
                    if (desc ? (a < c) : (a > c)) { key[i] = c; key[ixj] = a; }
                }
            }
            __syncthreads();
        }
    for (int m = tid; m < NWF; m += blockDim.x) {
        int idx = (NWIN - 1) - (int)(key[m] & 0xFFFULL);
        d_sel[b * NWF + m] = idx;
        atomicOr(&d_selmask[b * 128 + (idx >> 5)], 1u << (idx & 31));
    }
}

// ============ fused pool + selective copy ============
__global__ void poolcopy_kernel(const float* __restrict__ fm, float* __restrict__ out) {
    int bid = blockIdx.x;                // BB*CC*64
    int b = bid >> 13, c = (bid >> 6) & 127, p = bid & 63;
    int p0 = p >> 3, p1 = p & 7;
    __shared__ float red[128];
    __shared__ unsigned char wsel[64];
    int tid = threadIdx.x;
    if (tid < 64) {
        int wy = p0 * 8 + (tid >> 3), wx = p1 * 8 + (tid & 7);
        int wdw = wy * 64 + wx;
        wsel[tid] = (d_selmask[b * 128 + (wdw >> 5)] >> (wdw & 31)) & 1;
    }
    __syncthreads();
    size_t base_off = ((size_t)(b * CC + c) * HH + (size_t)p0 * 64) * WW + p1 * 64;
    const float* base = fm + base_off;
    float* ob = out + base_off;
    float s = 0.f;
    for (int e4 = tid; e4 < 1024; e4 += 128) {
        int r = e4 >> 4, col4 = (e4 & 15) * 4;
        float4 v = *(const float4*)(base + (size_t)r * WW + col4);
        s += (v.x + v.y) + (v.z + v.w);
        if (!wsel[(r >> 3) * 8 + (col4 >> 3)])
            *(float4*)(ob + (size_t)r * WW + col4) = v;
    }
    red[tid] = s;
    __syncthreads();
    for (int off = 64; off > 0; off >>= 1) {
        if (tid < off) red[tid] += red[tid + off];
        __syncthreads();
    }
    if (tid == 0) d_g[(b * 64 + p) * CC + c] = red[0] * (1.f / 4096.f);
}

// ============ global k/v projection ============
__global__ void kv2_kernel(const float* __restrict__ kvw) {
    __shared__ float g[64 * 128];
    __shared__ float wt[32 * 129];
    int bid = blockIdx.x;                // 16
    int b = bid >> 3, which = (bid >> 2) & 1, cg = bid & 3;
    int tid = threadIdx.x;
    for (int i = tid; i < 64 * 128; i += 256) g[i] = d_g[b * 64 * 128 + i];
    const float* wb = kvw + ((size_t)(which * 128 + cg * 32)) * 128;
    for (int i = tid; i < 32 * 128; i += 256) wt[(i >> 7) * 129 + (i & 127)] = wb[i];
    __syncthreads();
    int cl = tid & 31, c = cg * 32 + cl;
    int pb = (tid >> 5) * 8;
    float s[8] = {0.f,0.f,0.f,0.f,0.f,0.f,0.f,0.f};
    for (int k = 0; k < 128; k++) {
        float wv = wt[cl * 129 + k];
        #pragma unroll
        for (int q = 0; q < 8; q++) s[q] = fmaf(g[(pb + q) * 128 + k], wv, s[q]);
    }
    #pragma unroll
    for (int q = 0; q < 8; q++) {
        int p = pb + q;
        __nv_bfloat16 h = __float2bfloat16_rn(s[q]);
        if (which) d_vgtb[b][c * 64 + p] = h;
        else       d_kgb [b][p * 128 + c] = h;
    }
}

// weight copy: 512 threads, one matrix
__device__ __forceinline__ void copy_w512(const __nv_bfloat16* __restrict__ src,
                                          __nv_bfloat16* dst, int tid) {
    int r = tid >> 2, q = tid & 3;
    const uint4* s = (const uint4*)(src + r * 128 + q * 32);
    uint4* d = (uint4*)(dst + r * SA + q * 32);
    d[0] = __ldg(&s[0]); d[1] = __ldg(&s[1]); d[2] = __ldg(&s[2]); d[3] = __ldg(&s[3]);
}
// weight copy: 256 threads, one matrix
__device__ __forceinline__ void copy_w256(const __nv_bfloat16* __restrict__ src,
                                          __nv_bfloat16* dst, int t2) {
    int r = t2 >> 1, hf = t2 & 1;
    const uint4* s = (const uint4*)(src + r * 128 + hf * 64);
    uint4* d = (uint4*)(dst + r * SA + hf * 64);
    #pragma unroll
    for (int i = 0; i < 8; i++) d[i] = __ldg(&s[i]);
}

// ================= window kernel =================
__global__ __launch_bounds__(512) void window_kernel(
    const float* __restrict__ fm,
    const float* __restrict__ l0b, const float* __restrict__ pb,
    float* __restrict__ out)
{
    extern __shared__ __align__(16) unsigned char smc[];
    __nv_bfloat16* WFH = (__nv_bfloat16*)(smc + O_A);
    __nv_bfloat16* WFL = (__nv_bfloat16*)(smc + O_B);
    __nv_bfloat16* WTH = (__nv_bfloat16*)(smc + O_C);
    __nv_bfloat16* WTL = (__nv_bfloat16*)(smc + O_D);
    __nv_bfloat16* EB  = (__nv_bfloat16*)(smc + O_E);
    __nv_bfloat16* KG  = (__nv_bfloat16*)(smc + O_F);
    __nv_bfloat16* VGT = (__nv_bfloat16*)(smc + O_VGT);
    __nv_bfloat16* PB  = (__nv_bfloat16*)(smc + O_P);
    float* DUMP  = (float*)(smc + O_E);      // overlays EB+KG+VGT (dead when used)
    float* bias1 = (float*)(smc);
    float* bias2 = (float*)(smc + 512);

    const int tid  = threadIdx.x;
    const int w    = tid >> 5, lane = tid & 31;
    const int g    = lane >> 2, t = lane & 3;
    const int rb   = w & 7;
    const int row0 = rb * 16;
    const int nh   = w >> 3;
    const int cb   = nh * 64;
    const int wloc = rb >> 2;

    const int b  = blockIdx.x / NPAIR;
    const int pr = blockIdx.x % NPAIR;

    // ---- P0: gather + biases + kv images + qg weights ----
    {
        int rr = tid >> 2, q4 = tid & 3;
        int wsel = d_sel[b * NWF + pr * 2 + (rr >> 6)];
        int hy = wsel >> 6, wx = wsel & 63, tk = rr & 63;
        const float* fb = fm + (size_t)b * CC * HWSZ + (size_t)(hy * 8 + (tk >> 3)) * WW + wx * 8 + (tk & 7);
        #pragma unroll 4
        for (int i = 0; i < 32; i += 2) {
            int c = q4 * 32 + i;
            float x0 = __ldg(fb + (size_t)c * HWSZ);
            float x1 = __ldg(fb + (size_t)(c + 1) * HWSZ);
            uint32_t h, l; split2(x0, x1, h, l);
            *(uint32_t*)&WFH[rr * SA + c] = h;
            *(uint32_t*)&WFL[rr * SA + c] = l;
        }
        if (tid < 128) { bias1[tid] = l0b[tid]; bias2[tid] = pb[tid]; }
        const uint32_t* sk = (const uint32_t*)d_kgb[b];
        const uint32_t* sv = (const uint32_t*)d_vgtb[b];
        for (int i = tid; i < 4096; i += 512) {
            int p = i >> 6, cp = i & 63;
            *(uint32_t*)&KG[p * SA + cp * 2] = sk[i];
            int c2 = i >> 5, pp = i & 31;
            *(uint32_t*)&VGT[c2 * SP + pp * 2] = sv[i];
        }
        copy_w512(d_whi[0], WTH, tid);
    }
    __syncthreads();

#define STORE8(DST, STRIDE) { _Pragma("unroll") for (int nt = 0; nt < 8; nt++) { int c = cb + 8*nt + 2*t; \
    *(uint32_t*)&(DST)[(row0 + g) * (STRIDE) + c]     = pkf(acc[nt][0], acc[nt][1]); \
    *(uint32_t*)&(DST)[(row0 + 8 + g) * (STRIDE) + c] = pkf(acc[nt][2], acc[nt][3]); } }

// read master (hi+lo) at (row, col-pair)
#define MGET(ROW, C, OUT2) { \
    float2 _h = up2(*(uint32_t*)&WFH[(ROW) * SA + (C)]); \
    float2 _l = up2(*(uint32_t*)&WFL[(ROW) * SA + (C)]); \
    OUT2 = make_float2(_h.x + _l.x, _h.y + _l.y); }

#define MPUT(ROW, C, X0, X1) { uint32_t _hh, _ll; split2(X0, X1, _hh, _ll); \
    *(uint32_t*)&WFH[(ROW) * SA + (C)] = _hh; *(uint32_t*)&WFL[(ROW) * SA + (C)] = _ll; }

#define SOFTMAX64(SC) { \
    float mxa = -1e30f, mxb = -1e30f; \
    _Pragma("unroll") for (int nt = 0; nt < 8; nt++) { \
        (SC)[nt][0] *= SCALEF; (SC)[nt][1] *= SCALEF; (SC)[nt][2] *= SCALEF; (SC)[nt][3] *= SCALEF; \
        mxa = fmaxf(mxa, fmaxf((SC)[nt][0], (SC)[nt][1])); \
        mxb = fmaxf(mxb, fmaxf((SC)[nt][2], (SC)[nt][3])); } \
    mxa = fmaxf(mxa, __shfl_xor_sync(0xffffffffu, mxa, 1)); \
    mxa = fmaxf(mxa, __shfl_xor_sync(0xffffffffu, mxa, 2)); \
    mxb = fmaxf(mxb, __shfl_xor_sync(0xffffffffu, mxb, 1)); \
    mxb = fmaxf(mxb, __shfl_xor_sync(0xffffffffu, mxb, 2)); \
    float ea = 0.f, eb = 0.f; \
    _Pragma("unroll") for (int nt = 0; nt < 8; nt++) { \
        (SC)[nt][0] = __expf((SC)[nt][0] - mxa); (SC)[nt][1] = __expf((SC)[nt][1] - mxa); \
        (SC)[nt][2] = __expf((SC)[nt][2] - mxb); (SC)[nt][3] = __expf((SC)[nt][3] - mxb); \
        ea += (SC)[nt][0] + (SC)[nt][1]; eb += (SC)[nt][2] + (SC)[nt][3]; } \
    ea += __shfl_xor_sync(0xffffffffu, ea, 1); ea += __shfl_xor_sync(0xffffffffu, ea, 2); \
    eb += __shfl_xor_sync(0xffffffffu, eb, 1); eb += __shfl_xor_sync(0xffffffffu, eb, 2); \
    float ia = 1.f / ea, ib = 1.f / eb; \
    _Pragma("unroll") for (int nt = 0; nt < 8; nt++) { int c = 8*nt + 2*t; \
        *(uint32_t*)&PB[(row0 + g) * SP + c]     = pkf((SC)[nt][0] * ia, (SC)[nt][1] * ia); \
        *(uint32_t*)&PB[(row0 + 8 + g) * SP + c] = pkf((SC)[nt][2] * ib, (SC)[nt][3] * ib); } }

    // ---- P1: q = wf @ Wq_g^T ----
    {
        float acc[8][4]; ZACC(acc, 8);
        gpass<8, 8>(acc, WFH, SA, row0, WTH, SA, cb, g, t);
        STORE8(EB, SA);
    }
    __syncthreads();

    // ---- P2: scoresX + softmax (warps 0-7) | load l0 hi/lo (warps 8-15) ----
    if (nh == 0) {
        float sc[8][4]; ZACC(sc, 8);
        gpass<8, 8>(sc, EB, SA, row0, KG, SA, 0, g, t);
        SOFTMAX64(sc);
    } else {
        copy_w256(d_whi[1], WTH, tid - 256);
        copy_w256(d_wlo[0], WTL, tid - 256);
    }
    __syncthreads();

    // ---- P3: AV = P @ vgT^T ; wf += AV ----
    {
        float acc[8][4]; ZACC(acc, 8);
        gpass<8, 4>(acc, PB, SP, row0, VGT, SP, cb, g, t);
        #pragma unroll
        for (int nt = 0; nt < 8; nt++) {
            int c = cb + 8 * nt + 2 * t;
            float2 m0; MGET(row0 + g, c, m0);
            MPUT(row0 + g, c, m0.x + acc[nt][0], m0.y + acc[nt][1]);
            float2 m1; MGET(row0 + 8 + g, c, m1);
            MPUT(row0 + 8 + g, c, m1.x + acc[nt][2], m1.y + acc[nt][3]);
        }
    }
    __syncthreads();

    // ---- P4: MLP1 (3-pass split) ----
    {
        float acc[8][4]; ZACC(acc, 8);
        gpass<8, 8>(acc, WFH, SA, row0, WTH, SA, cb, g, t);
        gpass<8, 8>(acc, WFH, SA, row0, WTL, SA, cb, g, t);
        gpass<8, 8>(acc, WFL, SA, row0, WTH, SA, cb, g, t);
        #pragma unroll
        for (int nt = 0; nt < 8; nt++) {
            int c = cb + 8 * nt + 2 * t;
            float2 m0; MGET(row0 + g, c, m0);
            acc[nt][0] = m0.x + geluf(acc[nt][0] + bias1[c]);
            acc[nt][1] = m0.y + geluf(acc[nt][1] + bias1[c + 1]);
            float2 m1; MGET(row0 + 8 + g, c, m1);
            acc[nt][2] = m1.x + geluf(acc[nt][2] + bias1[c]);
            acc[nt][3] = m1.y + geluf(acc[nt][3] + bias1[c + 1]);
        }
        __syncthreads();            // all mma reads of WFH/WFL done
        #pragma unroll
        for (int nt = 0; nt < 8; nt++) {
            int c = cb + 8 * nt + 2 * t;
            MPUT(row0 + g, c, acc[nt][0], acc[nt][1]);
            MPUT(row0 + 8 + g, c, acc[nt][2], acc[nt][3]);
        }
    }
    __syncthreads();

    // ---- P5: load Wq2 -> WTH, Wk2 -> WTL ----
    if (tid < 256) copy_w256(d_whi[2], WTH, tid);
    else           copy_w256(d_whi[3], WTL, tid - 256);
    __syncthreads();

    // ---- P6: q2 (warps 0-7, NT=16) | k2 (warps 8-15, NT=16) ----
    {
        float acc[16][4]; ZACC(acc, 16);
        int r0 = rb * 16;
        if (nh == 0) {
            gpass<16, 8>(acc, WFH, SA, r0, WTH, SA, 0, g, t);
            #pragma unroll
            for (int nt = 0; nt < 16; nt++) { int c = 8*nt + 2*t;
                *(uint32_t*)&EB[(r0 + g) * SA + c]     = pkf(acc[nt][0], acc[nt][1]);
                *(uint32_t*)&EB[(r0 + 8 + g) * SA + c] = pkf(acc[nt][2], acc[nt][3]); }
        } else {
            gpass<16, 8>(acc, WFH, SA, r0, WTL, SA, 0, g, t);
            #pragma unroll
            for (int nt = 0; nt < 16; nt++) { int c = 8*nt + 2*t;
                *(uint32_t*)&KG[(r0 + g) * SA + c]     = pkf(acc[nt][0], acc[nt][1]);
                *(uint32_t*)&KG[(r0 + 8 + g) * SA + c] = pkf(acc[nt][2], acc[nt][3]); }
        }
    }
    __syncthreads();

    // ---- P7: scores2 + softmax (warps 0-7) | load Wv2 -> WTH (warps 8-15) ----
    if (nh == 0) {
        float sc[8][4]; ZACC(sc, 8);
        gpass<8, 8>(sc, EB, SA, row0, KG, SA, wloc * 64, g, t);
        SOFTMAX64(sc);
    } else {
        copy_w256(d_whi[4], WTH, tid - 256);
    }
    __syncthreads();

    // ---- P8: v2T = Wv @ wf^T (all warps) -> EB ----
    {
        float acc[8][4]; ZACC(acc, 8);
        gpass<8, 8>(acc, WTH, SA, row0, WFH, SA, cb, g, t);
        STORE8(EB, SA);
    }
    __syncthreads();

    // ---- P9: AV2 (warps 0-7, NT=16) | load pw hi/lo (warps 8-15) ----
    float av2[16][4];
    if (nh == 0) {
        ZACC(av2, 16);
        gpass<16, 4>(av2, PB, SP, row0, EB + wloc * 64, SA, 0, g, t);
    } else {
        copy_w256(d_whi[5], WTH, tid - 256);
        copy_w256(d_wlo[1], WTL, tid - 256);
    }
    __syncthreads();            // all AV2 reads of EB done

    // ---- P10: dump AV2 (warps 0-7) into DUMP (overlays EB/KG/VGT) ----
    if (nh == 0) {
        #pragma unroll
        for (int nt = 0; nt < 16; nt++) {
            int c = 8 * nt + 2 * t;
            *(float2*)&DUMP[(row0 + g) * SD + c]     = make_float2(av2[nt][0], av2[nt][1]);
            *(float2*)&DUMP[(row0 + 8 + g) * SD + c] = make_float2(av2[nt][2], av2[nt][3]);
        }
    }
    __syncthreads();

    // ---- P11: quirk: wf[t][j] += av[wloc*64 + j%64][2*(t%64) + j/64] ----
    {
        int rA = (row0 + g) & 63, rB = (row0 + 8 + g) & 63;
        int base = wloc * 64;
        #pragma unroll
        for (int nt = 0; nt < 8; nt++) {
            int c = cb + 8 * nt + 2 * t;
            float2 m0; MGET(row0 + g, c, m0);
            float2 m1; MGET(row0 + 8 + g, c, m1);
            #pragma unroll
            for (int e = 0; e < 2; e++) {
                int j = c + e;
                int rj = (base + (j & 63)) * SD + (j >> 6);
                float a0 = DUMP[rj + 2 * rA];
                float a1 = DUMP[rj + 2 * rB];
                if (e == 0) { m0.x += a0; m1.x += a1; }
                else        { m0.y += a0; m1.y += a1; }
            }
            MPUT(row0 + g, c, m0.x, m0.y);
            MPUT(row0 + 8 + g, c, m1.x, m1.y);
        }
    }
    __syncthreads();

    // ---- P12: MLP2 (3-pass, pw preloaded) + final ----
    {
        float acc[8][4]; ZACC(acc, 8);
        gpass<8, 8>(acc, WFH, SA, row0, WTH, SA, cb, g, t);
        gpass<8, 8>(acc, WFH, SA, row0, WTL, SA, cb, g, t);
        gpass<8, 8>(acc, WFL, SA, row0, WTH, SA, cb, g, t);
        #pragma unroll
        for (int nt = 0; nt < 8; nt++) {
            int c = cb + 8 * nt + 2 * t;
            float2 m0; MGET(row0 + g, c, m0);
            acc[nt][0] = m0.x + geluf(acc[nt][0] + bias2[c]);
            acc[nt][1] = m0.y + geluf(acc[nt][1] + bias2[c + 1]);
            float2 m1; MGET(row0 + 8 + g, c, m1);
            acc[nt][2] = m1.x + geluf(acc[nt][2] + bias2[c]);
            acc[nt][3] = m1.y + geluf(acc[nt][3] + bias2[c + 1]);
        }
        __syncthreads();        // all mma + DUMP reads done before overwrite
        #pragma unroll
        for (int nt = 0; nt < 8; nt++) {
            int c = cb + 8 * nt + 2 * t;
            *(float2*)&DUMP[(row0 + g) * SD + c]     = make_float2(acc[nt][0], acc[nt][1]);
            *(float2*)&DUMP[(row0 + 8 + g) * SD + c] = make_float2(acc[nt][2], acc[nt][3]);
        }
    }
    __syncthreads();

    // ---- P13: scatter ----
    {
        int rr = tid >> 2, q4 = tid & 3;
        int wsel = d_sel[b * NWF + pr * 2 + (rr >> 6)];
        int hy = wsel >> 6, wx = wsel & 63, tk = rr & 63;
        float* ob = out + (size_t)b * CC * HWSZ + (size_t)(hy * 8 + (tk >> 3)) * WW + wx * 8 + (tk & 7);
        #pragma unroll 8
        for (int i = 0; i < 32; i++) {
            int c = q4 * 32 + i;
            ob[(size_t)c * HWSZ] = DUMP[rr * SD + c];
        }
    }
#undef STORE8
#undef MGET
#undef MPUT
#undef SOFTMAX64
}

// =====================================================================
extern "C" void kernel_launch(void* const* d_in, const int* in_sizes, int n_in,
                              void* d_out, int out_size) {
    const float* fm   = (const float*)d_in[0];
    const float* unc  = (const float*)d_in[1];
    const float* qgw  = (const float*)d_in[2];
    const float* kvw  = (const float*)d_in[3];
    const float* l0w  = (const float*)d_in[4];
    const float* l0b  = (const float*)d_in[5];
    const float* qkvw = (const float*)d_in[6];
    const float* pw   = (const float*)d_in[7];
    const float* pb   = (const float*)d_in[8];
    float* out = (float*)d_out;

    cudaFuncSetAttribute(window_kernel, cudaFuncAttributeMaxDynamicSharedMemorySize, SMEM_SZ);

    select_prep_kernel<<<BB + 6, 1024>>>(unc, qgw, l0w, qkvw, pw);
    poolcopy_kernel<<<BB * CC * 64, 128>>>(fm, out);
    kv2_kernel<<<16, 256>>>(kvw);
    window_kernel<<<BB * NPAIR, 512, SMEM_SZ>>>(fm, l0b, pb, out);
}

// round 11
// speedup vs baseline: 3.9335x; 1.2583x over previous
#include <cuda_runtime.h>
#include <cuda_bf16.h>
#include <math.h>
#include <stdint.h>

#define BB   2
#define CC   128
#define HH   512
#define WW   512
#define NWIN 4096
#define NWF  1228
#define NPAIR (NWF/2)
#define HWSZ ((size_t)HH*(size_t)WW)
#define SCALEF 0.08838834764831845f

// strides (elements)
#define SA 136
#define SP 72
#define SD 132

// smem byte offsets
#define O_A   1024              // WFH 128x136 bf16
#define O_B   35840             // WFL
#define O_C   70656             // WTH
#define O_D   105472            // WTL
#define O_E   140288            // EB: q/q2/v2T ; DUMP (fp32 128x132) overlays E..E+67584
#define O_F   175104            // KG: kg (64 rows) / k2 (128 rows, spills into VGT: dead)
#define O_VGT (O_F+17408)
#define O_P   210944            // PB 128x72 bf16
#define SMEM_SZ 229376

// -------- device scratch --------
__device__ int   d_sel[BB * NWF];
__device__ unsigned d_selmask[BB * 128];
__device__ float d_g[BB * 64 * CC];
__device__ __nv_bfloat16 d_kgb[BB][64 * 128];
__device__ __nv_bfloat16 d_vgtb[BB][128 * 64];
// weight images (bf16): 0=qg 1=l0 2=q2 3=k2 4=v2 5=pw
__device__ __nv_bfloat16 d_whi[6][128 * 128];

// ---------------- helpers ----------------
__device__ __forceinline__ uint32_t pkf(float a, float b){
    __nv_bfloat162 t = __floats2bfloat162_rn(a, b);
    return *reinterpret_cast<uint32_t*>(&t);
}
__device__ __forceinline__ float2 up2(uint32_t u){
    __nv_bfloat162 b = *reinterpret_cast<__nv_bfloat162*>(&u);
    return make_float2(__bfloat162float(b.x), __bfloat162float(b.y));
}
__device__ __forceinline__ void split2(float x0, float x1, uint32_t& h, uint32_t& l){
    __nv_bfloat16 b0 = __float2bfloat16_rn(x0), b1 = __float2bfloat16_rn(x1);
    __nv_bfloat162 hb; hb.x = b0; hb.y = b1;
    h = *reinterpret_cast<uint32_t*>(&hb);
    l = pkf(x0 - __bfloat162float(b0), x1 - __bfloat162float(b1));
}
__device__ __forceinline__ float geluf(float x){
    return 0.5f * x * (1.f + erff(x * 0.70710678118654752f));
}
__device__ __forceinline__ void mma16816(float* d, const uint32_t* a, uint32_t b0, uint32_t b1){
    asm("mma.sync.aligned.m16n8k16.row.col.f32.bf16.bf16.f32 "
        "{%0,%1,%2,%3},{%4,%5,%6,%7},{%8,%9},{%0,%1,%2,%3};"
        : "+f"(d[0]), "+f"(d[1]), "+f"(d[2]), "+f"(d[3])
        : "r"(a[0]), "r"(a[1]), "r"(a[2]), "r"(a[3]), "r"(b0), "r"(b1));
}
__device__ __forceinline__ void ldsm4(uint32_t* r, uint32_t addr){
    asm volatile("ldmatrix.sync.aligned.m8n8.x4.shared.b16 {%0,%1,%2,%3}, [%4];"
        : "=r"(r[0]), "=r"(r[1]), "=r"(r[2]), "=r"(r[3]) : "r"(addr));
}

// ldmatrix-based GEMM pass: acc[NT][4]; A row-major [m][k] (rows row0..row0+15),
// B row-major [n][k] (rows bcol0..bcol0+NT*8-1), K = KS*16.
template<int NT, int KS>
__device__ __forceinline__ void gpassL(float (*acc)[4],
                                       const __nv_bfloat16* A, int sA, int row0,
                                       const __nv_bfloat16* B, int sB, int bcol0,
                                       int lane){
    // A: tiles {r0-7/k0, r8-15/k0, r0-7/k8, r8-15/k8}
    uint32_t aaddr = (uint32_t)__cvta_generic_to_shared(
        A + (row0 + (lane & 7) + (((lane >> 3) & 1) << 3)) * sA + ((lane >> 4) << 3));
    // B: tiles {n0-7/k0, n0-7/k8, n8-15/k0, n8-15/k8} per nt-pair
    uint32_t baddr = (uint32_t)__cvta_generic_to_shared(
        B + (bcol0 + (lane & 7) + ((lane >> 4) << 3)) * sB + (((lane >> 3) & 1) << 3));
    const uint32_t bstep = (uint32_t)(16 * sB * 2);
    #pragma unroll
    for (int ks = 0; ks < KS; ks++){
        uint32_t a[4]; ldsm4(a, aaddr + ks * 32);
        #pragma unroll
        for (int p = 0; p < NT / 2; p++){
            uint32_t bb[4]; ldsm4(bb, baddr + ks * 32 + p * bstep);
            mma16816(acc[2 * p],     a, bb[0], bb[1]);
            mma16816(acc[2 * p + 1], a, bb[2], bb[3]);
        }
    }
}

#define ZACC(A, N) { _Pragma("unroll") for (int _i = 0; _i < (N); _i++) { (A)[_i][0]=0.f;(A)[_i][1]=0.f;(A)[_i][2]=0.f;(A)[_i][3]=0.f; } }

// ============ selection (+score) + weight prep ============
__global__ void select_prep_kernel(const float* __restrict__ unc,
                                   const float* __restrict__ qgw,
                                   const float* __restrict__ l0w,
                                   const float* __restrict__ qkvw,
                                   const float* __restrict__ pw) {
    int tid = threadIdx.x;
    if (blockIdx.x >= BB) {
        int m = blockIdx.x - BB;
        const float* src = (m == 0) ? qgw : (m == 1) ? l0w :
                           (m < 5) ? qkvw + (size_t)(m - 2) * 16384 : pw;
        for (int i = tid; i < 16384; i += 1024)
            d_whi[m][i] = __float2bfloat16_rn(__ldg(&src[i]));
        return;
    }
    __shared__ unsigned long long key[NWIN];
    int b = blockIdx.x;
    for (int i = tid; i < 128; i += blockDim.x) d_selmask[b * 128 + i] = 0;
    for (int i = tid; i < NWIN; i += blockDim.x) {
        int hy = i >> 6, wx = i & 63;
        const float* base = unc + (size_t)b * HWSZ + (size_t)hy * 8 * WW + wx * 8;
        float s = 0.f;
        #pragma unroll
        for (int iy = 0; iy < 8; iy++)
            #pragma unroll
            for (int ix = 0; ix < 8; ix++) s += base[iy * WW + ix];
        unsigned int sb = __float_as_uint(s * (1.f / 64.f));
        key[i] = (((unsigned long long)sb) << 12) | (unsigned)(NWIN - 1 - i);
    }
    __syncthreads();
    for (int k = 2; k <= NWIN; k <<= 1)
        for (int j = k >> 1; j > 0; j >>= 1) {
            for (int i = tid; i < NWIN; i += blockDim.x) {
                int ixj = i ^ j;
                if (ixj > i) {
                    unsigned long long a = key[i], c = key[ixj];
                    bool desc = ((i & k) == 0);
                    if (desc ? (a < c) : (a > c)) { key[i] = c; key[ixj] = a; }
                }
            }
            __syncthreads();
        }
    for (int m = tid; m < NWF; m += blockDim.x) {
        int idx = (NWIN - 1) - (int)(key[m] & 0xFFFULL);
        d_sel[b * NWF + m] = idx;
        atomicOr(&d_selmask[b * 128 + (idx >> 5)], 1u << (idx & 31));
    }
}

// ============ fused pool + selective copy ============
__global__ void poolcopy_kernel(const float* __restrict__ fm, float* __restrict__ out) {
    int bid = blockIdx.x;
    int b = bid >> 13, c = (bid >> 6) & 127, p = bid & 63;
    int p0 = p >> 3, p1 = p & 7;
    __shared__ float red[128];
    __shared__ unsigned char wsel[64];
    int tid = threadIdx.x;
    if (tid < 64) {
        int wy = p0 * 8 + (tid >> 3), wx = p1 * 8 + (tid & 7);
        int wdw = wy * 64 + wx;
        wsel[tid] = (d_selmask[b * 128 + (wdw >> 5)] >> (wdw & 31)) & 1;
    }
    __syncthreads();
    size_t base_off = ((size_t)(b * CC + c) * HH + (size_t)p0 * 64) * WW + p1 * 64;
    const float* base = fm + base_off;
    float* ob = out + base_off;
    float s = 0.f;
    for (int e4 = tid; e4 < 1024; e4 += 128) {
        int r = e4 >> 4, col4 = (e4 & 15) * 4;
        float4 v = *(const float4*)(base + (size_t)r * WW + col4);
        s += (v.x + v.y) + (v.z + v.w);
        if (!wsel[(r >> 3) * 8 + (col4 >> 3)])
            *(float4*)(ob + (size_t)r * WW + col4) = v;
    }
    red[tid] = s;
    __syncthreads();
    for (int off = 64; off > 0; off >>= 1) {
        if (tid < off) red[tid] += red[tid + off];
        __syncthreads();
    }
    if (tid == 0) d_g[(b * 64 + p) * CC + c] = red[0] * (1.f / 4096.f);
}

// ============ global k/v projection ============
__global__ void kv2_kernel(const float* __restrict__ kvw) {
    __shared__ float g[64 * 128];
    __shared__ float wt[32 * 129];
    int bid = blockIdx.x;                // 16
    int b = bid >> 3, which = (bid >> 2) & 1, cg = bid & 3;
    int tid = threadIdx.x;
    for (int i = tid; i < 64 * 128; i += 256) g[i] = d_g[b * 64 * 128 + i];
    const float* wb = kvw + ((size_t)(which * 128 + cg * 32)) * 128;
    for (int i = tid; i < 32 * 128; i += 256) wt[(i >> 7) * 129 + (i & 127)] = wb[i];
    __syncthreads();
    int cl = tid & 31, c = cg * 32 + cl;
    int pb = (tid >> 5) * 8;
    float s[8] = {0.f,0.f,0.f,0.f,0.f,0.f,0.f,0.f};
    for (int k = 0; k < 128; k++) {
        float wv = wt[cl * 129 + k];
        #pragma unroll
        for (int q = 0; q < 8; q++) s[q] = fmaf(g[(pb + q) * 128 + k], wv, s[q]);
    }
    #pragma unroll
    for (int q = 0; q < 8; q++) {
        int p = pb + q;
        __nv_bfloat16 h = __float2bfloat16_rn(s[q]);
        if (which) d_vgtb[b][c * 64 + p] = h;
        else       d_kgb [b][p * 128 + c] = h;
    }
}

// weight copies
__device__ __forceinline__ void copy_w512(const __nv_bfloat16* __restrict__ src,
                                          __nv_bfloat16* dst, int tid) {
    int r = tid >> 2, q = tid & 3;
    const uint4* s = (const uint4*)(src + r * 128 + q * 32);
    uint4* d = (uint4*)(dst + r * SA + q * 32);
    d[0] = __ldg(&s[0]); d[1] = __ldg(&s[1]); d[2] = __ldg(&s[2]); d[3] = __ldg(&s[3]);
}
__device__ __forceinline__ void copy_w256(const __nv_bfloat16* __restrict__ src,
                                          __nv_bfloat16* dst, int t2) {
    int r = t2 >> 1, hf = t2 & 1;
    const uint4* s = (const uint4*)(src + r * 128 + hf * 64);
    uint4* d = (uint4*)(dst + r * SA + hf * 64);
    #pragma unroll
    for (int i = 0; i < 8; i++) d[i] = __ldg(&s[i]);
}

// ================= window kernel =================
__global__ __launch_bounds__(512) void window_kernel(
    const float* __restrict__ fm,
    const float* __restrict__ l0b, const float* __restrict__ pb,
    float* __restrict__ out)
{
    extern __shared__ __align__(16) unsigned char smc[];
    __nv_bfloat16* WFH = (__nv_bfloat16*)(smc + O_A);
    __nv_bfloat16* WFL = (__nv_bfloat16*)(smc + O_B);
    __nv_bfloat16* WTH = (__nv_bfloat16*)(smc + O_C);
    __nv_bfloat16* WTL = (__nv_bfloat16*)(smc + O_D);
    __nv_bfloat16* EB  = (__nv_bfloat16*)(smc + O_E);
    __nv_bfloat16* KG  = (__nv_bfloat16*)(smc + O_F);
    __nv_bfloat16* VGT = (__nv_bfloat16*)(smc + O_VGT);
    __nv_bfloat16* PB  = (__nv_bfloat16*)(smc + O_P);
    float* DUMP  = (float*)(smc + O_E);      // overlays EB/KG/VGT when dead
    float* bias1 = (float*)(smc);
    float* bias2 = (float*)(smc + 512);

    const int tid  = threadIdx.x;
    const int w    = tid >> 5, lane = tid & 31;
    const int g    = lane >> 2, t = lane & 3;
    const int rb   = w & 7;
    const int row0 = rb * 16;
    const int nh   = w >> 3;
    const int cb   = nh * 64;
    const int wloc = rb >> 2;

    const int b  = blockIdx.x / NPAIR;
    const int pr = blockIdx.x % NPAIR;

    // ---- P0: gather + biases + kv images + qg->WTH ----
    {
        int rr = tid >> 2, q4 = tid & 3;
        int wsel = d_sel[b * NWF + pr * 2 + (rr >> 6)];
        int hy = wsel >> 6, wx = wsel & 63, tk = rr & 63;
        const float* fb = fm + (size_t)b * CC * HWSZ + (size_t)(hy * 8 + (tk >> 3)) * WW + wx * 8 + (tk & 7);
        #pragma unroll 4
        for (int i = 0; i < 32; i += 2) {
            int c = q4 * 32 + i;
            float x0 = __ldg(fb + (size_t)c * HWSZ);
            float x1 = __ldg(fb + (size_t)(c + 1) * HWSZ);
            uint32_t h, l; split2(x0, x1, h, l);
            *(uint32_t*)&WFH[rr * SA + c] = h;
            *(uint32_t*)&WFL[rr * SA + c] = l;
        }
        if (tid < 128) { bias1[tid] = l0b[tid]; bias2[tid] = pb[tid]; }
        const uint32_t* sk = (const uint32_t*)d_kgb[b];
        const uint32_t* sv = (const uint32_t*)d_vgtb[b];
        for (int i = tid; i < 4096; i += 512) {
            int p = i >> 6, cp = i & 63;
            *(uint32_t*)&KG[p * SA + cp * 2] = sk[i];
            int c2 = i >> 5, pp = i & 31;
            *(uint32_t*)&VGT[c2 * SP + pp * 2] = sv[i];
        }
        copy_w512(d_whi[0], WTH, tid);
    }
    __syncthreads();

#define STORE8(DST, STRIDE) { _Pragma("unroll") for (int nt = 0; nt < 8; nt++) { int c = cb + 8*nt + 2*t; \
    *(uint32_t*)&(DST)[(row0 + g) * (STRIDE) + c]     = pkf(acc[nt][0], acc[nt][1]); \
    *(uint32_t*)&(DST)[(row0 + 8 + g) * (STRIDE) + c] = pkf(acc[nt][2], acc[nt][3]); } }

#define MGET(ROW, C, OUT2) { \
    float2 _h = up2(*(uint32_t*)&WFH[(ROW) * SA + (C)]); \
    float2 _l = up2(*(uint32_t*)&WFL[(ROW) * SA + (C)]); \
    OUT2 = make_float2(_h.x + _l.x, _h.y + _l.y); }

#define MPUT(ROW, C, X0, X1) { uint32_t _hh, _ll; split2(X0, X1, _hh, _ll); \
    *(uint32_t*)&WFH[(ROW) * SA + (C)] = _hh; *(uint32_t*)&WFL[(ROW) * SA + (C)] = _ll; }

#define SOFTMAX64(SC) { \
    float mxa = -1e30f, mxb = -1e30f; \
    _Pragma("unroll") for (int nt = 0; nt < 8; nt++) { \
        (SC)[nt][0] *= SCALEF; (SC)[nt][1] *= SCALEF; (SC)[nt][2] *= SCALEF; (SC)[nt][3] *= SCALEF; \
        mxa = fmaxf(mxa, fmaxf((SC)[nt][0], (SC)[nt][1])); \
        mxb = fmaxf(mxb, fmaxf((SC)[nt][2], (SC)[nt][3])); } \
    mxa = fmaxf(mxa, __shfl_xor_sync(0xffffffffu, mxa, 1)); \
    mxa = fmaxf(mxa, __shfl_xor_sync(0xffffffffu, mxa, 2)); \
    mxb = fmaxf(mxb, __shfl_xor_sync(0xffffffffu, mxb, 1)); \
    mxb = fmaxf(mxb, __shfl_xor_sync(0xffffffffu, mxb, 2)); \
    float ea = 0.f, eb = 0.f; \
    _Pragma("unroll") for (int nt = 0; nt < 8; nt++) { \
        (SC)[nt][0] = __expf((SC)[nt][0] - mxa); (SC)[nt][1] = __expf((SC)[nt][1] - mxa); \
        (SC)[nt][2] = __expf((SC)[nt][2] - mxb); (SC)[nt][3] = __expf((SC)[nt][3] - mxb); \
        ea += (SC)[nt][0] + (SC)[nt][1]; eb += (SC)[nt][2] + (SC)[nt][3]; } \
    ea += __shfl_xor_sync(0xffffffffu, ea, 1); ea += __shfl_xor_sync(0xffffffffu, ea, 2); \
    eb += __shfl_xor_sync(0xffffffffu, eb, 1); eb += __shfl_xor_sync(0xffffffffu, eb, 2); \
    float ia = 1.f / ea, ib = 1.f / eb; \
    _Pragma("unroll") for (int nt = 0; nt < 8; nt++) { int c = 8*nt + 2*t; \
        *(uint32_t*)&PB[(row0 + g) * SP + c]     = pkf((SC)[nt][0] * ia, (SC)[nt][1] * ia); \
        *(uint32_t*)&PB[(row0 + 8 + g) * SP + c] = pkf((SC)[nt][2] * ib, (SC)[nt][3] * ib); } }

    // ---- P1: q = wf @ Wq_g^T ----
    {
        float acc[8][4]; ZACC(acc, 8);
        gpassL<8, 8>(acc, WFH, SA, row0, WTH, SA, cb, lane);
        STORE8(EB, SA);
    }
    __syncthreads();

    // ---- P2: scoresX + softmax (nh0) | load l0->WTH, Wq2->WTL (nh1) ----
    if (nh == 0) {
        float sc[8][4]; ZACC(sc, 8);
        gpassL<8, 8>(sc, EB, SA, row0, KG, SA, 0, lane);
        SOFTMAX64(sc);
    } else {
        copy_w256(d_whi[1], WTH, tid - 256);
        copy_w256(d_whi[2], WTL, tid - 256);
    }
    __syncthreads();

    // ---- P3: AV = P @ vgT^T ; wf += AV ----
    {
        float acc[8][4]; ZACC(acc, 8);
        gpassL<8, 4>(acc, PB, SP, row0, VGT, SP, cb, lane);
        #pragma unroll
        for (int nt = 0; nt < 8; nt++) {
            int c = cb + 8 * nt + 2 * t;
            float2 m0; MGET(row0 + g, c, m0);
            MPUT(row0 + g, c, m0.x + acc[nt][0], m0.y + acc[nt][1]);
            float2 m1; MGET(row0 + 8 + g, c, m1);
            MPUT(row0 + 8 + g, c, m1.x + acc[nt][2], m1.y + acc[nt][3]);
        }
    }
    __syncthreads();

    // ---- P4: MLP1 (single-pass): wf += gelu(wf@l0^T + b1) ----
    {
        float acc[8][4]; ZACC(acc, 8);
        gpassL<8, 8>(acc, WFH, SA, row0, WTH, SA, cb, lane);
        #pragma unroll
        for (int nt = 0; nt < 8; nt++) {
            int c = cb + 8 * nt + 2 * t;
            float2 m0; MGET(row0 + g, c, m0);
            acc[nt][0] = m0.x + geluf(acc[nt][0] + bias1[c]);
            acc[nt][1] = m0.y + geluf(acc[nt][1] + bias1[c + 1]);
            float2 m1; MGET(row0 + 8 + g, c, m1);
            acc[nt][2] = m1.x + geluf(acc[nt][2] + bias1[c]);
            acc[nt][3] = m1.y + geluf(acc[nt][3] + bias1[c + 1]);
        }
        __syncthreads();            // all mma reads of WFH done (halves share rows)
        #pragma unroll
        for (int nt = 0; nt < 8; nt++) {
            int c = cb + 8 * nt + 2 * t;
            MPUT(row0 + g, c, acc[nt][0], acc[nt][1]);
            MPUT(row0 + 8 + g, c, acc[nt][2], acc[nt][3]);
        }
    }
    __syncthreads();

    // ---- P5: Wk2 -> WTH (all threads, short) ----
    copy_w512(d_whi[3], WTH, tid);
    __syncthreads();

    // ---- P6: q2 (nh0, NT=16 -> EB) | k2 (nh1, NT=16 -> KG) ----
    {
        float acc[16][4]; ZACC(acc, 16);
        if (nh == 0) {
            gpassL<16, 8>(acc, WFH, SA, row0, WTL, SA, 0, lane);
            #pragma unroll
            for (int nt = 0; nt < 16; nt++) { int c = 8*nt + 2*t;
                *(uint32_t*)&EB[(row0 + g) * SA + c]     = pkf(acc[nt][0], acc[nt][1]);
                *(uint32_t*)&EB[(row0 + 8 + g) * SA + c] = pkf(acc[nt][2], acc[nt][3]); }
        } else {
            gpassL<16, 8>(acc, WFH, SA, row0, WTH, SA, 0, lane);
            #pragma unroll
            for (int nt = 0; nt < 16; nt++) { int c = 8*nt + 2*t;
                *(uint32_t*)&KG[(row0 + g) * SA + c]     = pkf(acc[nt][0], acc[nt][1]);
                *(uint32_t*)&KG[(row0 + 8 + g) * SA + c] = pkf(acc[nt][2], acc[nt][3]); }
        }
    }
    __syncthreads();

    // ---- P7: scores2 + softmax (nh0) | Wv2 -> WTL (nh1) ----
    if (nh == 0) {
        float sc[8][4]; ZACC(sc, 8);
        gpassL<8, 8>(sc, EB, SA, row0, KG, SA, wloc * 64, lane);
        SOFTMAX64(sc);
    } else {
        copy_w256(d_whi[4], WTL, tid - 256);
    }
    __syncthreads();

    // ---- P8: v2T = Wv2 @ wf^T -> EB ----
    {
        float acc[8][4]; ZACC(acc, 8);
        gpassL<8, 8>(acc, WTL, SA, row0, WFH, SA, cb, lane);
        STORE8(EB, SA);
    }
    __syncthreads();

    // ---- P9: AV2 (nh0, NT=16) | pw -> WTH (nh1) ----
    float av2[16][4];
    if (nh == 0) {
        ZACC(av2, 16);
        gpassL<16, 4>(av2, PB, SP, row0, EB + wloc * 64, SA, 0, lane);
    } else {
        copy_w256(d_whi[5], WTH, tid - 256);
    }
    __syncthreads();            // all AV2 reads of EB done

    // ---- P10: dump AV2 -> DUMP (overlays EB/KG/VGT) ----
    if (nh == 0) {
        #pragma unroll
        for (int nt = 0; nt < 16; nt++) {
            int c = 8 * nt + 2 * t;
            *(float2*)&DUMP[(row0 + g) * SD + c]     = make_float2(av2[nt][0], av2[nt][1]);
            *(float2*)&DUMP[(row0 + 8 + g) * SD + c] = make_float2(av2[nt][2], av2[nt][3]);
        }
    }
    __syncthreads();

    // ---- P11: quirk: wf[t][j] += av[wloc*64 + j%64][2*(t%64) + j/64] ----
    {
        int rA = (row0 + g) & 63, rB = (row0 + 8 + g) & 63;
        int base = wloc * 64;
        #pragma unroll
        for (int nt = 0; nt < 8; nt++) {
            int c = cb + 8 * nt + 2 * t;
            float2 m0; MGET(row0 + g, c, m0);
            float2 m1; MGET(row0 + 8 + g, c, m1);
            #pragma unroll
            for (int e = 0; e < 2; e++) {
                int j = c + e;
                int rj = (base + (j & 63)) * SD + (j >> 6);
                float a0 = DUMP[rj + 2 * rA];
                float a1 = DUMP[rj + 2 * rB];
                if (e == 0) { m0.x += a0; m1.x += a1; }
                else        { m0.y += a0; m1.y += a1; }
            }
            MPUT(row0 + g, c, m0.x, m0.y);
            MPUT(row0 + 8 + g, c, m1.x, m1.y);
        }
    }
    __syncthreads();

    // ---- P12: MLP2 (single-pass) + final into DUMP ----
    {
        float acc[8][4]; ZACC(acc, 8);
        gpassL<8, 8>(acc, WFH, SA, row0, WTH, SA, cb, lane);
        #pragma unroll
        for (int nt = 0; nt < 8; nt++) {
            int c = cb + 8 * nt + 2 * t;
            float2 m0; MGET(row0 + g, c, m0);
            acc[nt][0] = m0.x + geluf(acc[nt][0] + bias2[c]);
            acc[nt][1] = m0.y + geluf(acc[nt][1] + bias2[c + 1]);
            float2 m1; MGET(row0 + 8 + g, c, m1);
            acc[nt][2] = m1.x + geluf(acc[nt][2] + bias2[c]);
            acc[nt][3] = m1.y + geluf(acc[nt][3] + bias2[c + 1]);
        }
        // DUMP region (EB/KG/VGT) not read by this phase: safe to write directly
        #pragma unroll
        for (int nt = 0; nt < 8; nt++) {
            int c = cb + 8 * nt + 2 * t;
            *(float2*)&DUMP[(row0 + g) * SD + c]     = make_float2(acc[nt][0], acc[nt][1]);
            *(float2*)&DUMP[(row0 + 8 + g) * SD + c] = make_float2(acc[nt][2], acc[nt][3]);
        }
    }
    __syncthreads();

    // ---- P13: scatter ----
    {
        int rr = tid >> 2, q4 = tid & 3;
        int wsel = d_sel[b * NWF + pr * 2 + (rr >> 6)];
        int hy = wsel >> 6, wx = wsel & 63, tk = rr & 63;
        float* ob = out + (size_t)b * CC * HWSZ + (size_t)(hy * 8 + (tk >> 3)) * WW + wx * 8 + (tk & 7);
        #pragma unroll 8
        for (int i = 0; i < 32; i++) {
            int c = q4 * 32 + i;
            ob[(size_t)c * HWSZ] = DUMP[rr * SD + c];
        }
    }
#undef STORE8
#undef MGET
#undef MPUT
#undef SOFTMAX64
}

// =====================================================================
extern "C" void kernel_launch(void* const* d_in, const int* in_sizes, int n_in,
                              void* d_out, int out_size) {
    const float* fm   = (const float*)d_in[0];
    const float* unc  = (const float*)d_in[1];
    const float* qgw  = (const float*)d_in[2];
    const float* kvw  = (const float*)d_in[3];
    const float* l0w  = (const float*)d_in[4];
    const float* l0b  = (const float*)d_in[5];
    const float* qkvw = (const float*)d_in[6];
    const float* pw   = (const float*)d_in[7];
    const float* pb   = (const float*)d_in[8];
    float* out = (float*)d_out;

    cudaFuncSetAttribute(window_kernel, cudaFuncAttributeMaxDynamicSharedMemorySize, SMEM_SZ);

    select_prep_kernel<<<BB + 6, 1024>>>(unc, qgw, l0w, qkvw, pw);
    poolcopy_kernel<<<BB * CC * 64, 128>>>(fm, out);
    kv2_kernel<<<16, 256>>>(kvw);
    window_kernel<<<BB * NPAIR, 512, SMEM_SZ>>>(fm, l0b, pb, out);
}

// round 12
// speedup vs baseline: 3.9569x; 1.0059x over previous
#include <cuda_runtime.h>
#include <cuda_bf16.h>
#include <math.h>
#include <stdint.h>

#define BB   2
#define CC   128
#define HH   512
#define WW   512
#define NWIN 4096
#define NWF  1228
#define NPAIR (NWF/2)
#define HWSZ ((size_t)HH*(size_t)WW)
#define SCALEF 0.08838834764831845f

// strides (elements)
#define SA 136
#define SP 72
#define SD 132

// smem byte offsets
#define O_A   1024              // WFH 128x136 bf16
#define O_B   35840             // WFL
#define O_C   70656             // WTH
#define O_D   105472            // WTL
#define O_E   140288            // EB ; DUMP (fp32 128x132 = 67584B) overlays E..207872
#define O_F   175104            // KG (kg 64 rows / k2 128 rows, spills into VGT: dead then)
#define O_VGT (O_F+17408)
#define O_P   210944            // PB 128x72 bf16
#define SMEM_SZ 229376

// -------- device scratch --------
__device__ int   d_sel[BB * NWF];
__device__ float d_g[BB * 64 * CC];
__device__ __nv_bfloat16 d_kgb[BB][64 * 128];
__device__ __nv_bfloat16 d_vgtb[BB][128 * 64];
// weight images (bf16): 0=qg 1=l0 2=q2 3=k2 4=v2 5=pw
__device__ __nv_bfloat16 d_whi[6][128 * 128];

// ---------------- helpers ----------------
__device__ __forceinline__ uint32_t pkf(float a, float b){
    __nv_bfloat162 t = __floats2bfloat162_rn(a, b);
    return *reinterpret_cast<uint32_t*>(&t);
}
__device__ __forceinline__ float2 up2(uint32_t u){
    __nv_bfloat162 b = *reinterpret_cast<__nv_bfloat162*>(&u);
    return make_float2(__bfloat162float(b.x), __bfloat162float(b.y));
}
__device__ __forceinline__ void split2(float x0, float x1, uint32_t& h, uint32_t& l){
    __nv_bfloat16 b0 = __float2bfloat16_rn(x0), b1 = __float2bfloat16_rn(x1);
    __nv_bfloat162 hb; hb.x = b0; hb.y = b1;
    h = *reinterpret_cast<uint32_t*>(&hb);
    l = pkf(x0 - __bfloat162float(b0), x1 - __bfloat162float(b1));
}
__device__ __forceinline__ float geluf(float x){
    return 0.5f * x * (1.f + erff(x * 0.70710678118654752f));
}
__device__ __forceinline__ void mma16816(float* d, const uint32_t* a, uint32_t b0, uint32_t b1){
    asm("mma.sync.aligned.m16n8k16.row.col.f32.bf16.bf16.f32 "
        "{%0,%1,%2,%3},{%4,%5,%6,%7},{%8,%9},{%0,%1,%2,%3};"
        : "+f"(d[0]), "+f"(d[1]), "+f"(d[2]), "+f"(d[3])
        : "r"(a[0]), "r"(a[1]), "r"(a[2]), "r"(a[3]), "r"(b0), "r"(b1));
}
__device__ __forceinline__ void ldsm4(uint32_t* r, uint32_t addr){
    asm volatile("ldmatrix.sync.aligned.m8n8.x4.shared.b16 {%0,%1,%2,%3}, [%4];"
        : "=r"(r[0]), "=r"(r[1]), "=r"(r[2]), "=r"(r[3]) : "r"(addr));
}

// Generic ldmatrix GEMM pass. A row-major [m][k] rows arow0..+MI*16-1,
// B row-major [n][k] rows bcol0..+NB*16-1, K = KS*16.
// acc[(mi*NB+nb)*2+half][4]: out row arow0+mi*16+g(+8), col (nb*2+half)*8+2t.
template<int MI, int NB, int KS>
__device__ __forceinline__ void gpassG(float (*acc)[4],
    const __nv_bfloat16* A, int sA, int arow0,
    const __nv_bfloat16* B, int sB, int bcol0, int lane)
{
    uint32_t aa[MI], bb[NB];
    uint32_t abase = (uint32_t)__cvta_generic_to_shared(
        A + (arow0 + (lane & 7) + (((lane >> 3) & 1) << 3)) * sA + ((lane >> 4) << 3));
    #pragma unroll
    for (int mi = 0; mi < MI; mi++) aa[mi] = abase + mi * 16 * sA * 2;
    uint32_t bbase = (uint32_t)__cvta_generic_to_shared(
        B + (bcol0 + (lane & 7) + ((lane >> 4) << 3)) * sB + (((lane >> 3) & 1) << 3));
    #pragma unroll
    for (int nb = 0; nb < NB; nb++) bb[nb] = bbase + nb * 16 * sB * 2;
    #pragma unroll
    for (int ks = 0; ks < KS; ks++) {
        uint32_t ar[MI][4];
        #pragma unroll
        for (int mi = 0; mi < MI; mi++) ldsm4(ar[mi], aa[mi] + ks * 32);
        #pragma unroll
        for (int nb = 0; nb < NB; nb++) {
            uint32_t rbv[4]; ldsm4(rbv, bb[nb] + ks * 32);
            #pragma unroll
            for (int mi = 0; mi < MI; mi++) {
                mma16816(acc[(mi * NB + nb) * 2],     ar[mi], rbv[0], rbv[1]);
                mma16816(acc[(mi * NB + nb) * 2 + 1], ar[mi], rbv[2], rbv[3]);
            }
        }
    }
}

#define ZACC(A, N) { _Pragma("unroll") for (int _i = 0; _i < (N); _i++) { (A)[_i][0]=0.f;(A)[_i][1]=0.f;(A)[_i][2]=0.f;(A)[_i][3]=0.f; } }

// ============ fused prep: sort+select | weight conv | pool + full copy ============
__global__ void prep_kernel(const float* __restrict__ unc,
                            const float* __restrict__ qgw,
                            const float* __restrict__ l0w,
                            const float* __restrict__ qkvw,
                            const float* __restrict__ pw,
                            const float* __restrict__ fm,
                            float* __restrict__ out) {
    __shared__ __align__(16) unsigned char sm[32768];
    int tid = threadIdx.x;               // 256
    int bid = blockIdx.x;
    if (bid < BB) {                      // ---- sort/select ----
        unsigned long long* key = (unsigned long long*)sm;
        int b = bid;
        for (int i = tid; i < NWIN; i += 256) {
            int hy = i >> 6, wx = i & 63;
            const float* base = unc + (size_t)b * HWSZ + (size_t)hy * 8 * WW + wx * 8;
            float s = 0.f;
            #pragma unroll
            for (int iy = 0; iy < 8; iy++)
                #pragma unroll
                for (int ix = 0; ix < 8; ix++) s += base[iy * WW + ix];
            unsigned int sb = __float_as_uint(s * (1.f / 64.f));
            key[i] = (((unsigned long long)sb) << 12) | (unsigned)(NWIN - 1 - i);
        }
        __syncthreads();
        for (int k = 2; k <= NWIN; k <<= 1)
            for (int j = k >> 1; j > 0; j >>= 1) {
                for (int i = tid; i < NWIN; i += 256) {
                    int ixj = i ^ j;
                    if (ixj > i) {
                        unsigned long long a = key[i], c = key[ixj];
                        bool desc = ((i & k) == 0);
                        if (desc ? (a < c) : (a > c)) { key[i] = c; key[ixj] = a; }
                    }
                }
                __syncthreads();
            }
        for (int m = tid; m < NWF; m += 256)
            d_sel[b * NWF + m] = (NWIN - 1) - (int)(key[m] & 0xFFFULL);
        return;
    }
    if (bid < BB + 6) {                  // ---- weight conversion ----
        int m = bid - BB;
        const float* src = (m == 0) ? qgw : (m == 1) ? l0w :
                           (m < 5) ? qkvw + (size_t)(m - 2) * 16384 : pw;
        for (int i = tid; i < 16384; i += 256)
            d_whi[m][i] = __float2bfloat16_rn(__ldg(&src[i]));
        return;
    }
    // ---- pool + full copy ----
    int pid = bid - BB - 6;              // BB*CC*64
    int b = pid >> 13, c = (pid >> 6) & 127, p = pid & 63;
    int p0 = p >> 3, p1 = p & 7;
    size_t base_off = ((size_t)(b * CC + c) * HH + (size_t)p0 * 64) * WW + p1 * 64;
    const float* base = fm + base_off;
    float* ob = out + base_off;
    float s = 0.f;
    for (int e4 = tid; e4 < 1024; e4 += 256) {
        int r = e4 >> 4, col4 = (e4 & 15) * 4;
        float4 v = *(const float4*)(base + (size_t)r * WW + col4);
        s += (v.x + v.y) + (v.z + v.w);
        *(float4*)(ob + (size_t)r * WW + col4) = v;
    }
    #pragma unroll
    for (int off = 16; off > 0; off >>= 1) s += __shfl_xor_sync(0xffffffffu, s, off);
    float* red = (float*)sm;
    if ((tid & 31) == 0) red[tid >> 5] = s;
    __syncthreads();
    if (tid == 0) {
        float tot = red[0];
        #pragma unroll
        for (int q = 1; q < 8; q++) tot += red[q];
        d_g[(b * 64 + p) * CC + c] = tot * (1.f / 4096.f);
    }
}

// ============ global k/v projection (64 blocks) ============
__global__ void kv2_kernel(const float* __restrict__ kvw) {
    __shared__ float g[16 * 128];
    __shared__ float wt[32 * 129];
    int bid = blockIdx.x;                // b(1) which(1) cg(2) pg(2)
    int b = bid >> 5, which = (bid >> 4) & 1, cg = (bid >> 2) & 3, pg = bid & 3;
    int tid = threadIdx.x;               // 256
    for (int i = tid; i < 16 * 128; i += 256) g[i] = d_g[b * 64 * 128 + pg * 16 * 128 + i];
    const float* wb = kvw + ((size_t)(which * 128 + cg * 32)) * 128;
    for (int i = tid; i < 32 * 128; i += 256) wt[(i >> 7) * 129 + (i & 127)] = wb[i];
    __syncthreads();
    int cl = tid & 31, c = cg * 32 + cl;
    int pi = tid >> 5;                   // 0..7
    float s0 = 0.f, s1 = 0.f;
    for (int k = 0; k < 128; k++) {
        float wv = wt[cl * 129 + k];
        s0 = fmaf(g[(pi * 2) * 128 + k], wv, s0);
        s1 = fmaf(g[(pi * 2 + 1) * 128 + k], wv, s1);
    }
    int p = pg * 16 + pi * 2;
    __nv_bfloat16 h0 = __float2bfloat16_rn(s0), h1 = __float2bfloat16_rn(s1);
    if (which) { d_vgtb[b][c * 64 + p] = h0; d_vgtb[b][c * 64 + p + 1] = h1; }
    else       { d_kgb [b][p * 128 + c] = h0; d_kgb [b][(p + 1) * 128 + c] = h1; }
}

// weight copies
__device__ __forceinline__ void copy_w512(const __nv_bfloat16* __restrict__ src,
                                          __nv_bfloat16* dst, int tid) {
    int r = tid >> 2, q = tid & 3;
    const uint4* s = (const uint4*)(src + r * 128 + q * 32);
    uint4* d = (uint4*)(dst + r * SA + q * 32);
    d[0] = __ldg(&s[0]); d[1] = __ldg(&s[1]); d[2] = __ldg(&s[2]); d[3] = __ldg(&s[3]);
}
__device__ __forceinline__ void copy_w256(const __nv_bfloat16* __restrict__ src,
                                          __nv_bfloat16* dst, int t2) {
    int r = t2 >> 1, hf = t2 & 1;
    const uint4* s = (const uint4*)(src + r * 128 + hf * 64);
    uint4* d = (uint4*)(dst + r * SA + hf * 64);
    #pragma unroll
    for (int i = 0; i < 8; i++) d[i] = __ldg(&s[i]);
}

// ================= window kernel =================
__global__ __launch_bounds__(512) void window_kernel(
    const float* __restrict__ fm,
    const float* __restrict__ l0b, const float* __restrict__ pb,
    float* __restrict__ out)
{
    extern __shared__ __align__(16) unsigned char smc[];
    __nv_bfloat16* WFH = (__nv_bfloat16*)(smc + O_A);
    __nv_bfloat16* WFL = (__nv_bfloat16*)(smc + O_B);
    __nv_bfloat16* WTH = (__nv_bfloat16*)(smc + O_C);
    __nv_bfloat16* WTL = (__nv_bfloat16*)(smc + O_D);
    __nv_bfloat16* EB  = (__nv_bfloat16*)(smc + O_E);
    __nv_bfloat16* KG  = (__nv_bfloat16*)(smc + O_F);
    __nv_bfloat16* VGT = (__nv_bfloat16*)(smc + O_VGT);
    __nv_bfloat16* PB  = (__nv_bfloat16*)(smc + O_P);
    float* DUMP  = (float*)(smc + O_E);
    float* bias1 = (float*)(smc);
    float* bias2 = (float*)(smc + 512);

    const int tid  = threadIdx.x;
    const int w    = tid >> 5, lane = tid & 31;
    const int g    = lane >> 2, t = lane & 3;
    // 32x32 tile mapping (16 warps)
    const int rb2  = w & 3,  cq = w >> 2;
    const int r32  = rb2 * 32, c32 = cq * 32;
    const int wl2  = rb2 >> 1;            // window of rows r32 (0: rows<64)
    // score mapping (warps 0-7)
    const int sr0  = (w & 7) * 16;
    const int swl  = (w & 7) >> 2;

    const int b  = blockIdx.x / NPAIR;
    const int pr = blockIdx.x % NPAIR;

    // ---- P0: gather + biases + kv images + qg->WTH ----
    {
        int rr = tid >> 2, q4 = tid & 3;
        int wsel = d_sel[b * NWF + pr * 2 + (rr >> 6)];
        int hy = wsel >> 6, wx = wsel & 63, tk = rr & 63;
        const float* fb = fm + (size_t)b * CC * HWSZ + (size_t)(hy * 8 + (tk >> 3)) * WW + wx * 8 + (tk & 7);
        #pragma unroll 4
        for (int i = 0; i < 32; i += 2) {
            int c = q4 * 32 + i;
            float x0 = __ldg(fb + (size_t)c * HWSZ);
            float x1 = __ldg(fb + (size_t)(c + 1) * HWSZ);
            uint32_t h, l; split2(x0, x1, h, l);
            *(uint32_t*)&WFH[rr * SA + c] = h;
            *(uint32_t*)&WFL[rr * SA + c] = l;
        }
        if (tid < 128) { bias1[tid] = l0b[tid]; bias2[tid] = pb[tid]; }
        const uint32_t* sk = (const uint32_t*)d_kgb[b];
        const uint32_t* sv = (const uint32_t*)d_vgtb[b];
        for (int i = tid; i < 4096; i += 512) {
            int p = i >> 6, cp = i & 63;
            *(uint32_t*)&KG[p * SA + cp * 2] = sk[i];
            int c2 = i >> 5, pp = i & 31;
            *(uint32_t*)&VGT[c2 * SP + pp * 2] = sv[i];
        }
        copy_w512(d_whi[0], WTH, tid);
    }
    __syncthreads();

#define MGET(ROW, C, OUT2) { \
    float2 _h = up2(*(uint32_t*)&WFH[(ROW) * SA + (C)]); \
    float2 _l = up2(*(uint32_t*)&WFL[(ROW) * SA + (C)]); \
    OUT2 = make_float2(_h.x + _l.x, _h.y + _l.y); }
#define MPUT(ROW, C, X0, X1) { uint32_t _hh, _ll; split2(X0, X1, _hh, _ll); \
    *(uint32_t*)&WFH[(ROW) * SA + (C)] = _hh; *(uint32_t*)&WFL[(ROW) * SA + (C)] = _ll; }

// store 32x32 acc tile to bf16 dst
#define STORE32(DST, S) { _Pragma("unroll") for (int mi = 0; mi < 2; mi++) \
    _Pragma("unroll") for (int nt = 0; nt < 4; nt++) { \
        float* a_ = acc[(mi * 2 + (nt >> 1)) * 2 + (nt & 1)]; \
        int r_ = r32 + mi * 16 + g, c_ = c32 + nt * 8 + 2 * t; \
        *(uint32_t*)&(DST)[r_ * (S) + c_]       = pkf(a_[0], a_[1]); \
        *(uint32_t*)&(DST)[(r_ + 8) * (S) + c_] = pkf(a_[2], a_[3]); } }

// softmax over 64 cols (score accs sc[nt 0..7][4]), rows (R0)+g / (R0)+8+g -> PB
#define SOFTMAX64(SC, R0) { \
    float mxa = -1e30f, mxb = -1e30f; \
    _Pragma("unroll") for (int nt = 0; nt < 8; nt++) { \
        (SC)[nt][0] *= SCALEF; (SC)[nt][1] *= SCALEF; (SC)[nt][2] *= SCALEF; (SC)[nt][3] *= SCALEF; \
        mxa = fmaxf(mxa, fmaxf((SC)[nt][0], (SC)[nt][1])); \
        mxb = fmaxf(mxb, fmaxf((SC)[nt][2], (SC)[nt][3])); } \
    mxa = fmaxf(mxa, __shfl_xor_sync(0xffffffffu, mxa, 1)); \
    mxa = fmaxf(mxa, __shfl_xor_sync(0xffffffffu, mxa, 2)); \
    mxb = fmaxf(mxb, __shfl_xor_sync(0xffffffffu, mxb, 1)); \
    mxb = fmaxf(mxb, __shfl_xor_sync(0xffffffffu, mxb, 2)); \
    float ea = 0.f, eb = 0.f; \
    _Pragma("unroll") for (int nt = 0; nt < 8; nt++) { \
        (SC)[nt][0] = __expf((SC)[nt][0] - mxa); (SC)[nt][1] = __expf((SC)[nt][1] - mxa); \
        (SC)[nt][2] = __expf((SC)[nt][2] - mxb); (SC)[nt][3] = __expf((SC)[nt][3] - mxb); \
        ea += (SC)[nt][0] + (SC)[nt][1]; eb += (SC)[nt][2] + (SC)[nt][3]; } \
    ea += __shfl_xor_sync(0xffffffffu, ea, 1); ea += __shfl_xor_sync(0xffffffffu, ea, 2); \
    eb += __shfl_xor_sync(0xffffffffu, eb, 1); eb += __shfl_xor_sync(0xffffffffu, eb, 2); \
    float ia = 1.f / ea, ib = 1.f / eb; \
    _Pragma("unroll") for (int nt = 0; nt < 8; nt++) { int c = 8 * nt + 2 * t; \
        *(uint32_t*)&PB[((R0) + g) * SP + c]     = pkf((SC)[nt][0] * ia, (SC)[nt][1] * ia); \
        *(uint32_t*)&PB[((R0) + 8 + g) * SP + c] = pkf((SC)[nt][2] * ib, (SC)[nt][3] * ib); } }

    // ---- P1: q = wf @ Wq_g^T -> EB ----
    {
        float acc[8][4]; ZACC(acc, 8);
        gpassG<2, 2, 8>(acc, WFH, SA, r32, WTH, SA, c32, lane);
        STORE32(EB, SA);
    }
    __syncthreads();

    // ---- P2: cross scores+softmax (w<8) | l0->WTH, Wq2->WTL (w>=8) ----
    if (w < 8) {
        float sc[8][4]; ZACC(sc, 8);
        gpassG<1, 4, 8>(sc, EB, SA, sr0, KG, SA, 0, lane);
        SOFTMAX64(sc, sr0);
    } else {
        copy_w256(d_whi[1], WTH, tid - 256);
        copy_w256(d_whi[2], WTL, tid - 256);
    }
    __syncthreads();

    // ---- P3: AV = P @ vgT^T ; wf += AV ----
    {
        float acc[8][4]; ZACC(acc, 8);
        gpassG<2, 2, 4>(acc, PB, SP, r32, VGT, SP, c32, lane);
        #pragma unroll
        for (int mi = 0; mi < 2; mi++)
            #pragma unroll
            for (int nt = 0; nt < 4; nt++) {
                float* a_ = acc[(mi * 2 + (nt >> 1)) * 2 + (nt & 1)];
                int r_ = r32 + mi * 16 + g, c_ = c32 + nt * 8 + 2 * t;
                float2 m0; MGET(r_, c_, m0);
                MPUT(r_, c_, m0.x + a_[0], m0.y + a_[1]);
                float2 m1; MGET(r_ + 8, c_, m1);
                MPUT(r_ + 8, c_, m1.x + a_[2], m1.y + a_[3]);
            }
    }
    __syncthreads();

    // ---- P4: MLP1 + (tail) Wk2->WTH ----
    {
        float acc[8][4]; ZACC(acc, 8);
        gpassG<2, 2, 8>(acc, WFH, SA, r32, WTH, SA, c32, lane);
        #pragma unroll
        for (int mi = 0; mi < 2; mi++)
            #pragma unroll
            for (int nt = 0; nt < 4; nt++) {
                float* a_ = acc[(mi * 2 + (nt >> 1)) * 2 + (nt & 1)];
                int r_ = r32 + mi * 16 + g, c_ = c32 + nt * 8 + 2 * t;
                float2 m0; MGET(r_, c_, m0);
                a_[0] = m0.x + geluf(a_[0] + bias1[c_]);
                a_[1] = m0.y + geluf(a_[1] + bias1[c_ + 1]);
                float2 m1; MGET(r_ + 8, c_, m1);
                a_[2] = m1.x + geluf(a_[2] + bias1[c_]);
                a_[3] = m1.y + geluf(a_[3] + bias1[c_ + 1]);
            }
        __syncthreads();             // all mma/master reads done
        #pragma unroll
        for (int mi = 0; mi < 2; mi++)
            #pragma unroll
            for (int nt = 0; nt < 4; nt++) {
                float* a_ = acc[(mi * 2 + (nt >> 1)) * 2 + (nt & 1)];
                int r_ = r32 + mi * 16 + g, c_ = c32 + nt * 8 + 2 * t;
                MPUT(r_, c_, a_[0], a_[1]);
                MPUT(r_ + 8, c_, a_[2], a_[3]);
            }
        copy_w512(d_whi[3], WTH, tid);   // Wk2 (l0 reads finished)
    }
    __syncthreads();

    // ---- P5: q2 (w<8, Wq2=WTL) -> EB | k2 (w>=8, Wk2=WTH) -> KG ----
    {
        float acc[16][4]; ZACC(acc, 16);
        int rq = (w & 3) * 32;
        int ch = ((w >> 2) & 1) * 64;
        if (w < 8) {
            gpassG<2, 4, 8>(acc, WFH, SA, rq, WTL, SA, ch, lane);
            #pragma unroll
            for (int mi = 0; mi < 2; mi++)
                #pragma unroll
                for (int nt = 0; nt < 8; nt++) {
                    float* a_ = acc[(mi * 4 + (nt >> 1)) * 2 + (nt & 1)];
                    int r_ = rq + mi * 16 + g, c_ = ch + nt * 8 + 2 * t;
                    *(uint32_t*)&EB[r_ * SA + c_]       = pkf(a_[0], a_[1]);
                    *(uint32_t*)&EB[(r_ + 8) * SA + c_] = pkf(a_[2], a_[3]);
                }
        } else {
            gpassG<2, 4, 8>(acc, WFH, SA, rq, WTH, SA, ch, lane);
            #pragma unroll
            for (int mi = 0; mi < 2; mi++)
                #pragma unroll
                for (int nt = 0; nt < 8; nt++) {
                    float* a_ = acc[(mi * 4 + (nt >> 1)) * 2 + (nt & 1)];
                    int r_ = rq + mi * 16 + g, c_ = ch + nt * 8 + 2 * t;
                    *(uint32_t*)&KG[r_ * SA + c_]       = pkf(a_[0], a_[1]);
                    *(uint32_t*)&KG[(r_ + 8) * SA + c_] = pkf(a_[2], a_[3]);
                }
        }
    }
    __syncthreads();

    // ---- P6: self scores+softmax (w<8) | Wv2->WTL (w>=8) ----
    if (w < 8) {
        float sc[8][4]; ZACC(sc, 8);
        gpassG<1, 4, 8>(sc, EB, SA, sr0, KG, SA, swl * 64, lane);
        SOFTMAX64(sc, sr0);
    } else {
        copy_w256(d_whi[4], WTL, tid - 256);
    }
    __syncthreads();

    // ---- P7: v2T = Wv2 @ wf^T -> EB ----
    {
        float acc[8][4]; ZACC(acc, 8);
        gpassG<2, 2, 8>(acc, WTL, SA, r32, WFH, SA, c32, lane);
        STORE32(EB, SA);
    }
    __syncthreads();

    // ---- P8: AV2 = P2 @ v2 (all 16 warps, 32x32) ----
    float av2[8][4];
    ZACC(av2, 8);
    gpassG<2, 2, 4>(av2, PB, SP, r32, EB + wl2 * 64, SA, c32, lane);
    __syncthreads();                     // EB reads done (DUMP overlays it)

    // ---- P9: dump AV2 -> DUMP ----
    #pragma unroll
    for (int mi = 0; mi < 2; mi++)
        #pragma unroll
        for (int nt = 0; nt < 4; nt++) {
            float* a_ = av2[(mi * 2 + (nt >> 1)) * 2 + (nt & 1)];
            int r_ = r32 + mi * 16 + g, c_ = c32 + nt * 8 + 2 * t;
            *(float2*)&DUMP[r_ * SD + c_]       = make_float2(a_[0], a_[1]);
            *(float2*)&DUMP[(r_ + 8) * SD + c_] = make_float2(a_[2], a_[3]);
        }
    __syncthreads();

    // ---- P10: quirk (w<8, full 128 cols of rows sr0..) | pw->WTH (w>=8) ----
    if (w < 8) {
        #pragma unroll
        for (int half = 0; half < 2; half++) {
            int rr_ = sr0 + half * 8 + g;
            int rA = rr_ & 63;
            #pragma unroll
            for (int nt = 0; nt < 16; nt++) {
                int c = nt * 8 + 2 * t;
                float2 m; MGET(rr_, c, m);
                int j0 = c, j1 = c + 1;
                m.x += DUMP[(swl * 64 + (j0 & 63)) * SD + (j0 >> 6) + 2 * rA];
                m.y += DUMP[(swl * 64 + (j1 & 63)) * SD + (j1 >> 6) + 2 * rA];
                MPUT(rr_, c, m.x, m.y);
            }
        }
    } else {
        copy_w256(d_whi[5], WTH, tid - 256);
    }
    __syncthreads();

    // ---- P11: MLP2 -> DUMP (final values) ----
    {
        float acc[8][4]; ZACC(acc, 8);
        gpassG<2, 2, 8>(acc, WFH, SA, r32, WTH, SA, c32, lane);
        #pragma unroll
        for (int mi = 0; mi < 2; mi++)
            #pragma unroll
            for (int nt = 0; nt < 4; nt++) {
                float* a_ = acc[(mi * 2 + (nt >> 1)) * 2 + (nt & 1)];
                int r_ = r32 + mi * 16 + g, c_ = c32 + nt * 8 + 2 * t;
                float2 m0; MGET(r_, c_, m0);
                float2 m1; MGET(r_ + 8, c_, m1);
                *(float2*)&DUMP[r_ * SD + c_] = make_float2(
                    m0.x + geluf(a_[0] + bias2[c_]), m0.y + geluf(a_[1] + bias2[c_ + 1]));
                *(float2*)&DUMP[(r_ + 8) * SD + c_] = make_float2(
                    m1.x + geluf(a_[2] + bias2[c_]), m1.y + geluf(a_[3] + bias2[c_ + 1]));
            }
    }
    __syncthreads();

    // ---- P12: scatter ----
    {
        int rr = tid >> 2, q4 = tid & 3;
        int wsel = d_sel[b * NWF + pr * 2 + (rr >> 6)];
        int hy = wsel >> 6, wx = wsel & 63, tk = rr & 63;
        float* ob = out + (size_t)b * CC * HWSZ + (size_t)(hy * 8 + (tk >> 3)) * WW + wx * 8 + (tk & 7);
        #pragma unroll 8
        for (int i = 0; i < 32; i++) {
            int c = q4 * 32 + i;
            ob[(size_t)c * HWSZ] = DUMP[rr * SD + c];
        }
    }
#undef STORE32
#undef MGET
#undef MPUT
#undef SOFTMAX64
}

// =====================================================================
extern "C" void kernel_launch(void* const* d_in, const int* in_sizes, int n_in,
                              void* d_out, int out_size) {
    const float* fm   = (const float*)d_in[0];
    const float* unc  = (const float*)d_in[1];
    const float* qgw  = (const float*)d_in[2];
    const float* kvw  = (const float*)d_in[3];
    const float* l0w  = (const float*)d_in[4];
    const float* l0b  = (const float*)d_in[5];
    const float* qkvw = (const float*)d_in[6];
    const float* pw   = (const float*)d_in[7];
    const float* pb   = (const float*)d_in[8];
    float* out = (float*)d_out;

    cudaFuncSetAttribute(window_kernel, cudaFuncAttributeMaxDynamicSharedMemorySize, SMEM_SZ);

    prep_kernel<<<BB + 6 + BB * CC * 64, 256>>>(unc, qgw, l0w, qkvw, pw, fm, out);
    kv2_kernel<<<64, 256>>>(kvw);
    window_kernel<<<BB * NPAIR, 512, SMEM_SZ>>>(fm, l0b, pb, out);
}